// round 1
// baseline (speedup 1.0000x reference)
#include <cuda_runtime.h>
#include <cuda_bf16.h>
#include <math.h>

#define N_NODES 100000
#define N_EDGES 1600000
#define F_IN 512
#define HID 156
#define N_CLS 7

// ---------------- scratch (device globals; no allocation allowed) ----------
__device__ float g_h[(size_t)N_NODES * HID];     // 62.4 MB  xW1 result
__device__ float g_h2[(size_t)N_NODES * N_CLS];  // 2.8 MB   relu(agg1+b1)@W2
__device__ float g_dis[N_NODES];                 // 1/sqrt(deg)
__device__ int   g_deg[N_NODES];
__device__ int   g_rowptr[N_NODES + 1];
__device__ int   g_cursor[N_NODES];
__device__ int   g_col[N_EDGES];                 // CSR by dst, holds src ids
__device__ int   g_blocksums[128];

#define SCAN_BLOCKS ((N_NODES + 1023) / 1024)    // 98

// ---------------- degree / CSR build ---------------------------------------
__global__ void k_init_deg() {
    int i = blockIdx.x * blockDim.x + threadIdx.x;
    if (i < N_NODES) g_deg[i] = 1;   // self-loop
}

__global__ void k_count(const int* __restrict__ dst) {
    int e = blockIdx.x * blockDim.x + threadIdx.x;
    if (e < N_EDGES) atomicAdd(&g_deg[dst[e]], 1);
}

__global__ void k_scan1() {
    __shared__ int sh[1024];
    int t = threadIdx.x;
    int i = blockIdx.x * 1024 + t;
    int v = (i < N_NODES) ? (g_deg[i] - 1) : 0;
    sh[t] = v;
    __syncthreads();
    for (int off = 1; off < 1024; off <<= 1) {
        int add = (t >= off) ? sh[t - off] : 0;
        __syncthreads();
        sh[t] += add;
        __syncthreads();
    }
    int incl = sh[t];
    if (i < N_NODES) g_rowptr[i] = incl - v;      // exclusive within block
    if (t == 1023) g_blocksums[blockIdx.x] = incl;
}

__global__ void k_scan2() {
    // tiny: sequential exclusive scan of 98 block sums
    int s = 0;
    for (int b = 0; b < SCAN_BLOCKS; b++) {
        int t = g_blocksums[b];
        g_blocksums[b] = s;
        s += t;
    }
}

__global__ void k_scan3() {
    int i = blockIdx.x * blockDim.x + threadIdx.x;
    if (i < N_NODES) {
        int r = g_rowptr[i] + g_blocksums[i >> 10];
        g_rowptr[i] = r;
        g_cursor[i] = r;
        g_dis[i] = rsqrtf((float)g_deg[i]);
        if (i == 0) g_rowptr[N_NODES] = N_EDGES;
    }
}

__global__ void k_fill(const int* __restrict__ src, const int* __restrict__ dst) {
    int e = blockIdx.x * blockDim.x + threadIdx.x;
    if (e < N_EDGES) {
        int d = dst[e];
        int pos = atomicAdd(&g_cursor[d], 1);
        g_col[pos] = src[e];
    }
}

// ---------------- GEMM1: h = x @ W1   (100000x512 @ 512x156) ---------------
// Block tile 64(M) x 160(N, 156 valid) x 32(K). 256 threads, 4x10 per thread.
#define BM 64
#define BK 32
#define BN 160

__global__ __launch_bounds__(256) void k_gemm(const float* __restrict__ x,
                                              const float* __restrict__ W1) {
    __shared__ float As[BM][36];   // row stride 36 floats (144B, 16B aligned)
    __shared__ float Bs[BK][BN];

    int tid = threadIdx.x;
    int bm = blockIdx.x * BM;
    int tm = tid >> 4;     // 0..15 -> 4 rows each
    int tn = tid & 15;     // 0..15 -> cols tn + 16*j

    float acc[4][10];
#pragma unroll
    for (int i = 0; i < 4; i++)
#pragma unroll
        for (int j = 0; j < 10; j++) acc[i][j] = 0.f;

    for (int k0 = 0; k0 < F_IN; k0 += BK) {
        // load A: 64x32 floats = 512 float4, 2 per thread
#pragma unroll
        for (int t = 0; t < 2; t++) {
            int idx = tid + t * 256;       // 0..511
            int r = idx >> 3;              // 8 float4 per row
            int kg = idx & 7;
            int grow = bm + r;
            float4 v;
            if (grow < N_NODES)
                v = *(const float4*)(x + (size_t)grow * F_IN + k0 + kg * 4);
            else
                v = make_float4(0.f, 0.f, 0.f, 0.f);
            *(float4*)&As[r][kg * 4] = v;
        }
        // load B: 32x160 (156 valid) = 5120 floats, 20 per thread
#pragma unroll
        for (int j = 0; j < 20; j++) {
            int idx = tid + j * 256;
            int k = idx / BN;
            int c = idx - k * BN;
            Bs[k][c] = (c < HID) ? W1[(size_t)(k0 + k) * HID + c] : 0.f;
        }
        __syncthreads();

#pragma unroll
        for (int k = 0; k < BK; k++) {
            float a[4], b[10];
#pragma unroll
            for (int i = 0; i < 4; i++) a[i] = As[tm * 4 + i][k];
#pragma unroll
            for (int j = 0; j < 10; j++) b[j] = Bs[k][tn + 16 * j];
#pragma unroll
            for (int i = 0; i < 4; i++)
#pragma unroll
                for (int j = 0; j < 10; j++)
                    acc[i][j] = fmaf(a[i], b[j], acc[i][j]);
        }
        __syncthreads();
    }

#pragma unroll
    for (int i = 0; i < 4; i++) {
        int r = bm + tm * 4 + i;
        if (r >= N_NODES) continue;
#pragma unroll
        for (int j = 0; j < 10; j++) {
            int c = tn + 16 * j;
            if (c < HID) g_h[(size_t)r * HID + c] = acc[i][j];
        }
    }
}

// ---------------- Agg1 fused with relu + W2 projection ----------------------
// warp per node: u = relu(dis_i * (sum_j dis_j*h_j + dis_i*h_i) + b1)
// then g_h2[i] = u @ W2 (156x7) via warp reduction.
__global__ __launch_bounds__(256) void k_agg1(const float* __restrict__ b1,
                                              const float* __restrict__ W2) {
    __shared__ float W2s[HID * N_CLS];
    __shared__ float b1s[HID];
    int tid = threadIdx.x;
    for (int i = tid; i < HID * N_CLS; i += 256) W2s[i] = W2[i];
    for (int i = tid; i < HID; i += 256) b1s[i] = b1[i];
    __syncthreads();

    int warp = tid >> 5, lane = tid & 31;
    int node = blockIdx.x * 8 + warp;
    if (node >= N_NODES) return;

    float acc[5] = {0.f, 0.f, 0.f, 0.f, 0.f};
    int beg = g_rowptr[node], end = g_rowptr[node + 1];
    for (int e = beg; e < end; e++) {
        int s = g_col[e];
        float ds = __ldg(&g_dis[s]);
        const float* hp = g_h + (size_t)s * HID;
#pragma unroll
        for (int m = 0; m < 5; m++) {
            int c = lane + 32 * m;
            if (c < HID) acc[m] = fmaf(ds, __ldg(hp + c), acc[m]);
        }
    }
    float di = g_dis[node];
    {
        const float* hp = g_h + (size_t)node * HID;
#pragma unroll
        for (int m = 0; m < 5; m++) {
            int c = lane + 32 * m;
            if (c < HID) acc[m] = fmaf(di, hp[c], acc[m]);
        }
    }
    float u[5];
#pragma unroll
    for (int m = 0; m < 5; m++) {
        int c = lane + 32 * m;
        u[m] = (c < HID) ? fmaxf(fmaf(di, acc[m], b1s[c]), 0.f) : 0.f;
    }

    float outk[N_CLS];
#pragma unroll
    for (int k = 0; k < N_CLS; k++) {
        float p = 0.f;
#pragma unroll
        for (int m = 0; m < 5; m++) {
            int c = lane + 32 * m;
            if (c < HID) p = fmaf(u[m], W2s[c * N_CLS + k], p);
        }
#pragma unroll
        for (int o = 16; o > 0; o >>= 1) p += __shfl_xor_sync(0xffffffffu, p, o);
        outk[k] = p;
    }
    if (lane == 0) {
#pragma unroll
        for (int k = 0; k < N_CLS; k++) g_h2[(size_t)node * N_CLS + k] = outk[k];
    }
}

// ---------------- Agg2 + bias + log_softmax ---------------------------------
__global__ __launch_bounds__(256) void k_agg2(const float* __restrict__ b2,
                                              float* __restrict__ out) {
    int i = blockIdx.x * blockDim.x + threadIdx.x;
    if (i >= N_NODES) return;

    float acc[N_CLS];
#pragma unroll
    for (int k = 0; k < N_CLS; k++) acc[k] = 0.f;

    int beg = g_rowptr[i], end = g_rowptr[i + 1];
    for (int e = beg; e < end; e++) {
        int s = g_col[e];
        float ds = __ldg(&g_dis[s]);
        const float* p = g_h2 + (size_t)s * N_CLS;
#pragma unroll
        for (int k = 0; k < N_CLS; k++) acc[k] = fmaf(ds, __ldg(p + k), acc[k]);
    }
    float di = g_dis[i];
    {
        const float* p = g_h2 + (size_t)i * N_CLS;
#pragma unroll
        for (int k = 0; k < N_CLS; k++) acc[k] = fmaf(di, p[k], acc[k]);
    }
    float v[N_CLS];
#pragma unroll
    for (int k = 0; k < N_CLS; k++) v[k] = fmaf(di, acc[k], __ldg(b2 + k));

    float m = v[0];
#pragma unroll
    for (int k = 1; k < N_CLS; k++) m = fmaxf(m, v[k]);
    float s = 0.f;
#pragma unroll
    for (int k = 0; k < N_CLS; k++) s += expf(v[k] - m);
    float lse = m + logf(s);
#pragma unroll
    for (int k = 0; k < N_CLS; k++) out[(size_t)i * N_CLS + k] = v[k] - lse;
}

// ---------------- launch -----------------------------------------------------
extern "C" void kernel_launch(void* const* d_in, const int* in_sizes, int n_in,
                              void* d_out, int out_size) {
    const float* x  = (const float*)d_in[0];
    const int*   ei = (const int*)d_in[1];
    const float* W1 = (const float*)d_in[2];
    const float* b1 = (const float*)d_in[3];
    const float* W2 = (const float*)d_in[4];
    const float* b2 = (const float*)d_in[5];
    float* out = (float*)d_out;

    const int* src = ei;
    const int* dst = ei + N_EDGES;

    k_init_deg<<<(N_NODES + 255) / 256, 256>>>();
    k_count<<<(N_EDGES + 255) / 256, 256>>>(dst);
    k_scan1<<<SCAN_BLOCKS, 1024>>>();
    k_scan2<<<1, 1>>>();
    k_scan3<<<(N_NODES + 255) / 256, 256>>>();
    k_fill<<<(N_EDGES + 255) / 256, 256>>>(src, dst);

    k_gemm<<<(N_NODES + BM - 1) / BM, 256>>>(x, W1);
    k_agg1<<<(N_NODES + 7) / 8, 256>>>(b1, W2);
    k_agg2<<<(N_NODES + 255) / 256, 256>>>(b2, out);
}

// round 4
// speedup vs baseline: 2.0158x; 2.0158x over previous
#include <cuda_runtime.h>
#include <cuda_bf16.h>
#include <math.h>
#include <stdint.h>

#define N_NODES 100000
#define N_EDGES 1600000
#define F_IN 512
#define HID 156
#define N_CLS 7
#define NPAD 160

// ---------------- scratch (device globals; no allocation allowed) ----------
__device__ __align__(16) float g_h[(size_t)N_NODES * HID];     // 62.4 MB
__device__ __align__(16) float g_h2[(size_t)N_NODES * N_CLS];  // 2.8 MB
__device__ float g_dis[N_NODES];
__device__ int   g_deg[N_NODES];
__device__ int   g_rowptr[N_NODES + 1];
__device__ int   g_cursor[N_NODES];
__device__ int   g_col[N_EDGES];
__device__ int   g_blocksums[128];
__device__ __align__(16) __nv_bfloat16 g_wt_hi[NPAD * F_IN];   // W1^T hi, [160][512]
__device__ __align__(16) __nv_bfloat16 g_wt_lo[NPAD * F_IN];   // W1^T lo

#define SCAN_BLOCKS ((N_NODES + 1023) / 1024)    // 98

// ---------------- degree / CSR build ---------------------------------------
__global__ void k_init_deg() {
    int i = blockIdx.x * blockDim.x + threadIdx.x;
    if (i < N_NODES) g_deg[i] = 1;
}
__global__ void k_count(const int* __restrict__ dst) {
    int e = blockIdx.x * blockDim.x + threadIdx.x;
    if (e < N_EDGES) atomicAdd(&g_deg[dst[e]], 1);
}
__global__ void k_scan1() {
    __shared__ int sh[1024];
    int t = threadIdx.x;
    int i = blockIdx.x * 1024 + t;
    int v = (i < N_NODES) ? (g_deg[i] - 1) : 0;
    sh[t] = v;
    __syncthreads();
    for (int off = 1; off < 1024; off <<= 1) {
        int add = (t >= off) ? sh[t - off] : 0;
        __syncthreads();
        sh[t] += add;
        __syncthreads();
    }
    int incl = sh[t];
    if (i < N_NODES) g_rowptr[i] = incl - v;
    if (t == 1023) g_blocksums[blockIdx.x] = incl;
}
__global__ void k_scan2() {
    int s = 0;
    for (int b = 0; b < SCAN_BLOCKS; b++) {
        int t = g_blocksums[b];
        g_blocksums[b] = s;
        s += t;
    }
}
__global__ void k_scan3() {
    int i = blockIdx.x * blockDim.x + threadIdx.x;
    if (i < N_NODES) {
        int r = g_rowptr[i] + g_blocksums[i >> 10];
        g_rowptr[i] = r;
        g_cursor[i] = r;
        g_dis[i] = rsqrtf((float)g_deg[i]);
        if (i == 0) g_rowptr[N_NODES] = N_EDGES;
    }
}
__global__ void k_fill(const int* __restrict__ src, const int* __restrict__ dst) {
    int e = blockIdx.x * blockDim.x + threadIdx.x;
    if (e < N_EDGES) {
        int d = dst[e];
        int pos = atomicAdd(&g_cursor[d], 1);
        g_col[pos] = src[e];
    }
}

// ---------------- W1 transpose + bf16 hi/lo split: g_wt[n][k] ---------------
__global__ void k_prepw(const float* __restrict__ W1) {
    int idx = blockIdx.x * 256 + threadIdx.x;
    if (idx >= NPAD * F_IN) return;
    int n = idx >> 9;
    int k = idx & 511;
    float v = (n < HID) ? W1[(size_t)k * HID + n] : 0.f;
    __nv_bfloat16 hi = __float2bfloat16(v);
    __nv_bfloat16 lo = __float2bfloat16(v - __bfloat162float(hi));
    g_wt_hi[idx] = hi;
    g_wt_lo[idx] = lo;
}

// ---------------- GEMM1 via mma.sync bf16-split -----------------------------
// CTA: 128(M) x 160(N) x 512(K), chunks of BK=32. 8 warps = 4(M) x 2(N).
// Warp tile 32x80 = 2 x 10 m16n8k16 fragments. hi*hi + hi*lo + lo*hi.
// SMEM (bf16, padded row stride 40 elems = 80B, conflict-free):
//   Ahi[128][40] @0      (10240 B)
//   Alo[128][40] @10240
//   Bhi[160][40] @20480  (12800 B)   B stored [n][k] (k contiguous)
//   Blo[160][40] @33280
// Epilogue reuses smem as float Ds[128][164] (83968 B).
#define A_HI 0
#define A_LO 10240
#define B_HI 20480
#define B_LO 33280
#define SMEM_GEMM 84992

__device__ __forceinline__ void mma16816(float* d, const uint32_t* a,
                                         uint32_t b0, uint32_t b1) {
    asm volatile(
        "mma.sync.aligned.m16n8k16.row.col.f32.bf16.bf16.f32 "
        "{%0,%1,%2,%3}, {%4,%5,%6,%7}, {%8,%9}, {%0,%1,%2,%3};"
        : "+f"(d[0]), "+f"(d[1]), "+f"(d[2]), "+f"(d[3])
        : "r"(a[0]), "r"(a[1]), "r"(a[2]), "r"(a[3]), "r"(b0), "r"(b1));
}

__global__ void __launch_bounds__(256) k_gemm_mma(const float* __restrict__ x) {
    extern __shared__ char smem[];
    int tid = threadIdx.x, wid = tid >> 5, lane = tid & 31;
    int g = lane >> 2, tg = lane & 3;
    int wm = wid & 3, wn = wid >> 2;            // 4 M-warps x 2 N-warps
    int bm = blockIdx.x * 128;

    float acc[2][10][4];
#pragma unroll
    for (int i = 0; i < 2; i++)
#pragma unroll
        for (int j = 0; j < 10; j++)
#pragma unroll
            for (int q = 0; q < 4; q++) acc[i][j][q] = 0.f;

    float4 pa[4];
    uint2  pbh[5], pbl[5];

    // ---- prefetch chunk 0 ----
#pragma unroll
    for (int j = 0; j < 4; j++) {
        int idx = tid + j * 256;           // 0..1023
        int r = idx >> 3, f4 = idx & 7;
        pa[j] = make_float4(0.f, 0.f, 0.f, 0.f);
        if (bm + r < N_NODES)
            pa[j] = *(const float4*)(x + (size_t)(bm + r) * F_IN + f4 * 4);
    }
#pragma unroll
    for (int j = 0; j < 5; j++) {
        int idx = tid + j * 256;           // 0..1279
        int n = idx >> 3, q = idx & 7;
        pbh[j] = *(const uint2*)((const char*)g_wt_hi + (size_t)n * 1024 + q * 8);
        pbl[j] = *(const uint2*)((const char*)g_wt_lo + (size_t)n * 1024 + q * 8);
    }

    // ---- store chunk 0 to smem ----
#pragma unroll
    for (int j = 0; j < 4; j++) {
        int idx = tid + j * 256;
        int r = idx >> 3, f4 = idx & 7;
        float4 v = pa[j];
        __nv_bfloat162 h01 = __floats2bfloat162_rn(v.x, v.y);
        __nv_bfloat162 h23 = __floats2bfloat162_rn(v.z, v.w);
        __nv_bfloat162 l01 = __floats2bfloat162_rn(
            v.x - __bfloat162float(__low2bfloat16(h01)),
            v.y - __bfloat162float(__high2bfloat16(h01)));
        __nv_bfloat162 l23 = __floats2bfloat162_rn(
            v.z - __bfloat162float(__low2bfloat16(h23)),
            v.w - __bfloat162float(__high2bfloat16(h23)));
        uint2 hw, lw;
        hw.x = *(uint32_t*)&h01; hw.y = *(uint32_t*)&h23;
        lw.x = *(uint32_t*)&l01; lw.y = *(uint32_t*)&l23;
        *(uint2*)(smem + A_HI + r * 80 + f4 * 8) = hw;
        *(uint2*)(smem + A_LO + r * 80 + f4 * 8) = lw;
    }
#pragma unroll
    for (int j = 0; j < 5; j++) {
        int idx = tid + j * 256;
        int n = idx >> 3, q = idx & 7;
        *(uint2*)(smem + B_HI + n * 80 + q * 8) = pbh[j];
        *(uint2*)(smem + B_LO + n * 80 + q * 8) = pbl[j];
    }
    __syncthreads();

#pragma unroll 1
    for (int c = 0; c < 16; c++) {
        // prefetch next chunk into registers (overlaps with compute below)
        if (c + 1 < 16) {
            int k0 = (c + 1) * 32;
#pragma unroll
            for (int j = 0; j < 4; j++) {
                int idx = tid + j * 256;
                int r = idx >> 3, f4 = idx & 7;
                pa[j] = make_float4(0.f, 0.f, 0.f, 0.f);
                if (bm + r < N_NODES)
                    pa[j] = *(const float4*)(x + (size_t)(bm + r) * F_IN + k0 + f4 * 4);
            }
#pragma unroll
            for (int j = 0; j < 5; j++) {
                int idx = tid + j * 256;
                int n = idx >> 3, q = idx & 7;
                pbh[j] = *(const uint2*)((const char*)g_wt_hi + (size_t)n * 1024 + k0 * 2 + q * 8);
                pbl[j] = *(const uint2*)((const char*)g_wt_lo + (size_t)n * 1024 + k0 * 2 + q * 8);
            }
        }

        // compute on current smem chunk: 2 k16 steps
#pragma unroll
        for (int kk = 0; kk < 2; kk++) {
            int kb = kk * 32;               // byte offset within 64B row chunk
            uint32_t afr[2][2][4];          // [mf][hi/lo][4]
#pragma unroll
            for (int mf = 0; mf < 2; mf++) {
                int r0 = wm * 32 + mf * 16 + g;
                int o0 = r0 * 80 + kb + tg * 4;
                int o1 = (r0 + 8) * 80 + kb + tg * 4;
                afr[mf][0][0] = *(const uint32_t*)(smem + A_HI + o0);
                afr[mf][0][1] = *(const uint32_t*)(smem + A_HI + o1);
                afr[mf][0][2] = *(const uint32_t*)(smem + A_HI + o0 + 16);
                afr[mf][0][3] = *(const uint32_t*)(smem + A_HI + o1 + 16);
                afr[mf][1][0] = *(const uint32_t*)(smem + A_LO + o0);
                afr[mf][1][1] = *(const uint32_t*)(smem + A_LO + o1);
                afr[mf][1][2] = *(const uint32_t*)(smem + A_LO + o0 + 16);
                afr[mf][1][3] = *(const uint32_t*)(smem + A_LO + o1 + 16);
            }
#pragma unroll
            for (int nf = 0; nf < 10; nf++) {
                int cl = wn * 80 + nf * 8 + g;
                int ob = cl * 80 + kb + tg * 4;
                uint32_t bh0 = *(const uint32_t*)(smem + B_HI + ob);
                uint32_t bh1 = *(const uint32_t*)(smem + B_HI + ob + 16);
                uint32_t bl0 = *(const uint32_t*)(smem + B_LO + ob);
                uint32_t bl1 = *(const uint32_t*)(smem + B_LO + ob + 16);
#pragma unroll
                for (int mf = 0; mf < 2; mf++) {
                    mma16816(acc[mf][nf], afr[mf][0], bh0, bh1);  // hi*hi
                    mma16816(acc[mf][nf], afr[mf][0], bl0, bl1);  // hi*lo
                    mma16816(acc[mf][nf], afr[mf][1], bh0, bh1);  // lo*hi
                }
            }
        }
        __syncthreads();

        if (c + 1 < 16) {
#pragma unroll
            for (int j = 0; j < 4; j++) {
                int idx = tid + j * 256;
                int r = idx >> 3, f4 = idx & 7;
                float4 v = pa[j];
                __nv_bfloat162 h01 = __floats2bfloat162_rn(v.x, v.y);
                __nv_bfloat162 h23 = __floats2bfloat162_rn(v.z, v.w);
                __nv_bfloat162 l01 = __floats2bfloat162_rn(
                    v.x - __bfloat162float(__low2bfloat16(h01)),
                    v.y - __bfloat162float(__high2bfloat16(h01)));
                __nv_bfloat162 l23 = __floats2bfloat162_rn(
                    v.z - __bfloat162float(__low2bfloat16(h23)),
                    v.w - __bfloat162float(__high2bfloat16(h23)));
                uint2 hw, lw;
                hw.x = *(uint32_t*)&h01; hw.y = *(uint32_t*)&h23;
                lw.x = *(uint32_t*)&l01; lw.y = *(uint32_t*)&l23;
                *(uint2*)(smem + A_HI + r * 80 + f4 * 8) = hw;
                *(uint2*)(smem + A_LO + r * 80 + f4 * 8) = lw;
            }
#pragma unroll
            for (int j = 0; j < 5; j++) {
                int idx = tid + j * 256;
                int n = idx >> 3, q = idx & 7;
                *(uint2*)(smem + B_HI + n * 80 + q * 8) = pbh[j];
                *(uint2*)(smem + B_LO + n * 80 + q * 8) = pbl[j];
            }
            __syncthreads();
        }
    }

    // ---- epilogue: accs -> smem Ds[128][164] -> coalesced g_h stores ----
    float* Ds = (float*)smem;
#pragma unroll
    for (int mf = 0; mf < 2; mf++) {
        int r = wm * 32 + mf * 16 + g;
#pragma unroll
        for (int nf = 0; nf < 10; nf++) {
            int cc = wn * 80 + nf * 8 + tg * 2;
            *(float2*)&Ds[r * 164 + cc]       = make_float2(acc[mf][nf][0], acc[mf][nf][1]);
            *(float2*)&Ds[(r + 8) * 164 + cc] = make_float2(acc[mf][nf][2], acc[mf][nf][3]);
        }
    }
    __syncthreads();

    int rows = N_NODES - bm;
    if (rows > 128) rows = 128;
    int total = rows * HID;
    for (int i = tid; i < total; i += 256) {
        int r = i / HID, cc = i - r * HID;
        g_h[(size_t)(bm + r) * HID + cc] = Ds[r * 164 + cc];
    }
}

// ---------------- Agg1 fused with relu + W2 projection ----------------------
__global__ void __launch_bounds__(256) k_agg1(const float* __restrict__ b1,
                                              const float* __restrict__ W2) {
    __shared__ float W2s[HID * N_CLS];
    __shared__ float b1s[HID];
    int tid = threadIdx.x;
    for (int i = tid; i < HID * N_CLS; i += 256) W2s[i] = W2[i];
    for (int i = tid; i < HID; i += 256) b1s[i] = b1[i];
    __syncthreads();

    int warp = tid >> 5, lane = tid & 31;
    int node = blockIdx.x * 8 + warp;
    if (node >= N_NODES) return;

    float acc[5] = {0.f, 0.f, 0.f, 0.f, 0.f};
    int beg = g_rowptr[node], end = g_rowptr[node + 1];
    for (int e = beg; e < end; e++) {
        int s = g_col[e];
        float ds = __ldg(&g_dis[s]);
        const float* hp = g_h + (size_t)s * HID;
#pragma unroll
        for (int m = 0; m < 5; m++) {
            int c = lane + 32 * m;
            if (c < HID) acc[m] = fmaf(ds, __ldg(hp + c), acc[m]);
        }
    }
    float di = g_dis[node];
    {
        const float* hp = g_h + (size_t)node * HID;
#pragma unroll
        for (int m = 0; m < 5; m++) {
            int c = lane + 32 * m;
            if (c < HID) acc[m] = fmaf(di, hp[c], acc[m]);
        }
    }
    float u[5];
#pragma unroll
    for (int m = 0; m < 5; m++) {
        int c = lane + 32 * m;
        u[m] = (c < HID) ? fmaxf(fmaf(di, acc[m], b1s[c]), 0.f) : 0.f;
    }

    float outk[N_CLS];
#pragma unroll
    for (int k = 0; k < N_CLS; k++) {
        float p = 0.f;
#pragma unroll
        for (int m = 0; m < 5; m++) {
            int c = lane + 32 * m;
            if (c < HID) p = fmaf(u[m], W2s[c * N_CLS + k], p);
        }
#pragma unroll
        for (int o = 16; o > 0; o >>= 1) p += __shfl_xor_sync(0xffffffffu, p, o);
        outk[k] = p;
    }
    if (lane == 0) {
#pragma unroll
        for (int k = 0; k < N_CLS; k++) g_h2[(size_t)node * N_CLS + k] = outk[k];
    }
}

// ---------------- Agg2 + bias + log_softmax ---------------------------------
__global__ void __launch_bounds__(256) k_agg2(const float* __restrict__ b2,
                                              float* __restrict__ out) {
    int i = blockIdx.x * blockDim.x + threadIdx.x;
    if (i >= N_NODES) return;

    float acc[N_CLS];
#pragma unroll
    for (int k = 0; k < N_CLS; k++) acc[k] = 0.f;

    int beg = g_rowptr[i], end = g_rowptr[i + 1];
    for (int e = beg; e < end; e++) {
        int s = g_col[e];
        float ds = __ldg(&g_dis[s]);
        const float* p = g_h2 + (size_t)s * N_CLS;
#pragma unroll
        for (int k = 0; k < N_CLS; k++) acc[k] = fmaf(ds, __ldg(p + k), acc[k]);
    }
    float di = g_dis[i];
    {
        const float* p = g_h2 + (size_t)i * N_CLS;
#pragma unroll
        for (int k = 0; k < N_CLS; k++) acc[k] = fmaf(di, p[k], acc[k]);
    }
    float v[N_CLS];
#pragma unroll
    for (int k = 0; k < N_CLS; k++) v[k] = fmaf(di, acc[k], __ldg(b2 + k));

    float m = v[0];
#pragma unroll
    for (int k = 1; k < N_CLS; k++) m = fmaxf(m, v[k]);
    float s = 0.f;
#pragma unroll
    for (int k = 0; k < N_CLS; k++) s += expf(v[k] - m);
    float lse = m + logf(s);
#pragma unroll
    for (int k = 0; k < N_CLS; k++) out[(size_t)i * N_CLS + k] = v[k] - lse;
}

// ---------------- launch -----------------------------------------------------
extern "C" void kernel_launch(void* const* d_in, const int* in_sizes, int n_in,
                              void* d_out, int out_size) {
    const float* x  = (const float*)d_in[0];
    const int*   ei = (const int*)d_in[1];
    const float* W1 = (const float*)d_in[2];
    const float* b1 = (const float*)d_in[3];
    const float* W2 = (const float*)d_in[4];
    const float* b2 = (const float*)d_in[5];
    float* out = (float*)d_out;

    const int* src = ei;
    const int* dst = ei + N_EDGES;

    cudaFuncSetAttribute(k_gemm_mma, cudaFuncAttributeMaxDynamicSharedMemorySize, SMEM_GEMM);

    k_prepw<<<(NPAD * F_IN + 255) / 256, 256>>>(W1);
    k_init_deg<<<(N_NODES + 255) / 256, 256>>>();
    k_count<<<(N_EDGES + 255) / 256, 256>>>(dst);
    k_scan1<<<SCAN_BLOCKS, 1024>>>();
    k_scan2<<<1, 1>>>();
    k_scan3<<<(N_NODES + 255) / 256, 256>>>();
    k_fill<<<(N_EDGES + 255) / 256, 256>>>(src, dst);

    k_gemm_mma<<<(N_NODES + 127) / 128, 256, SMEM_GEMM>>>(x);
    k_agg1<<<(N_NODES + 7) / 8, 256>>>(b1, W2);
    k_agg2<<<(N_NODES + 255) / 256, 256>>>(b2, out);
}

// round 5
// speedup vs baseline: 2.0243x; 1.0042x over previous
#include <cuda_runtime.h>
#include <cuda_bf16.h>
#include <math.h>
#include <stdint.h>

#define N_NODES 100000
#define N_EDGES 1600000
#define F_IN 512
#define HID 156
#define N_CLS 7
#define NPAD 160

// ---------------- scratch (device globals; no allocation allowed) ----------
__device__ __align__(16) float g_h[(size_t)N_NODES * HID];     // 62.4 MB
__device__ __align__(16) float g_h2[(size_t)N_NODES * N_CLS];  // 2.8 MB
__device__ float g_dis[N_NODES];
__device__ int   g_deg[N_NODES];
__device__ int   g_rowptr[N_NODES + 1];
__device__ int   g_cursor[N_NODES];
__device__ int   g_col[N_EDGES];
__device__ int   g_blocksums[128];
__device__ __align__(16) __nv_bfloat16 g_wt_hi[NPAD * F_IN];   // W1^T hi, [160][512]
__device__ __align__(16) __nv_bfloat16 g_wt_lo[NPAD * F_IN];   // W1^T lo

#define SCAN_BLOCKS ((N_NODES + 1023) / 1024)    // 98

// ---------------- degree / CSR build ---------------------------------------
__global__ void k_init_deg() {
    int i = blockIdx.x * blockDim.x + threadIdx.x;
    if (i < N_NODES) g_deg[i] = 1;
}
__global__ void k_count(const int* __restrict__ dst) {
    int e = blockIdx.x * blockDim.x + threadIdx.x;
    if (e < N_EDGES) atomicAdd(&g_deg[dst[e]], 1);
}
__global__ void k_scan1() {
    __shared__ int sh[1024];
    int t = threadIdx.x;
    int i = blockIdx.x * 1024 + t;
    int v = (i < N_NODES) ? (g_deg[i] - 1) : 0;
    sh[t] = v;
    __syncthreads();
    for (int off = 1; off < 1024; off <<= 1) {
        int add = (t >= off) ? sh[t - off] : 0;
        __syncthreads();
        sh[t] += add;
        __syncthreads();
    }
    int incl = sh[t];
    if (i < N_NODES) g_rowptr[i] = incl - v;
    if (t == 1023) g_blocksums[blockIdx.x] = incl;
}
__global__ void k_scan2() {
    int s = 0;
    for (int b = 0; b < SCAN_BLOCKS; b++) {
        int t = g_blocksums[b];
        g_blocksums[b] = s;
        s += t;
    }
}
__global__ void k_scan3() {
    int i = blockIdx.x * blockDim.x + threadIdx.x;
    if (i < N_NODES) {
        int r = g_rowptr[i] + g_blocksums[i >> 10];
        g_rowptr[i] = r;
        g_cursor[i] = r;
        g_dis[i] = rsqrtf((float)g_deg[i]);
        if (i == 0) g_rowptr[N_NODES] = N_EDGES;
    }
}
__global__ void k_fill(const int* __restrict__ src, const int* __restrict__ dst) {
    int e = blockIdx.x * blockDim.x + threadIdx.x;
    if (e < N_EDGES) {
        int d = dst[e];
        int pos = atomicAdd(&g_cursor[d], 1);
        g_col[pos] = src[e];
    }
}

// ---------------- W1 transpose + bf16 hi/lo split: g_wt[n][k] ---------------
__global__ void k_prepw(const float* __restrict__ W1) {
    int idx = blockIdx.x * 256 + threadIdx.x;
    if (idx >= NPAD * F_IN) return;
    int n = idx >> 9;
    int k = idx & 511;
    float v = (n < HID) ? W1[(size_t)k * HID + n] : 0.f;
    __nv_bfloat16 hi = __float2bfloat16(v);
    __nv_bfloat16 lo = __float2bfloat16(v - __bfloat162float(hi));
    g_wt_hi[idx] = hi;
    g_wt_lo[idx] = lo;
}

// ---------------- GEMM1 via mma.sync bf16-split -----------------------------
// CTA: 128(M) x 160(N) x 512(K), chunks of BK=32. 8 warps = 4(M) x 2(N).
// Warp tile 32x80 = 2 x 10 m16n8k16 fragments. hi*hi + hi*lo + lo*hi.
// SMEM (bf16, padded row stride 40 elems = 80B, conflict-free):
//   Ahi[128][40] @0      (10240 B)
//   Alo[128][40] @10240
//   Bhi[160][40] @20480  (12800 B)   B stored [n][k] (k contiguous)
//   Blo[160][40] @33280
// Epilogue reuses smem as float Ds[128][164] (83968 B).
#define A_HI 0
#define A_LO 10240
#define B_HI 20480
#define B_LO 33280
#define SMEM_GEMM 84992

__device__ __forceinline__ void mma16816(float* d, const uint32_t* a,
                                         uint32_t b0, uint32_t b1) {
    asm volatile(
        "mma.sync.aligned.m16n8k16.row.col.f32.bf16.bf16.f32 "
        "{%0,%1,%2,%3}, {%4,%5,%6,%7}, {%8,%9}, {%0,%1,%2,%3};"
        : "+f"(d[0]), "+f"(d[1]), "+f"(d[2]), "+f"(d[3])
        : "r"(a[0]), "r"(a[1]), "r"(a[2]), "r"(a[3]), "r"(b0), "r"(b1));
}

__global__ void __launch_bounds__(256) k_gemm_mma(const float* __restrict__ x) {
    extern __shared__ char smem[];
    int tid = threadIdx.x, wid = tid >> 5, lane = tid & 31;
    int g = lane >> 2, tg = lane & 3;
    int wm = wid & 3, wn = wid >> 2;            // 4 M-warps x 2 N-warps
    int bm = blockIdx.x * 128;

    float acc[2][10][4];
#pragma unroll
    for (int i = 0; i < 2; i++)
#pragma unroll
        for (int j = 0; j < 10; j++)
#pragma unroll
            for (int q = 0; q < 4; q++) acc[i][j][q] = 0.f;

    float4 pa[4];
    uint2  pbh[5], pbl[5];

    // ---- prefetch chunk 0 ----
#pragma unroll
    for (int j = 0; j < 4; j++) {
        int idx = tid + j * 256;           // 0..1023
        int r = idx >> 3, f4 = idx & 7;
        pa[j] = make_float4(0.f, 0.f, 0.f, 0.f);
        if (bm + r < N_NODES)
            pa[j] = *(const float4*)(x + (size_t)(bm + r) * F_IN + f4 * 4);
    }
#pragma unroll
    for (int j = 0; j < 5; j++) {
        int idx = tid + j * 256;           // 0..1279
        int n = idx >> 3, q = idx & 7;
        pbh[j] = *(const uint2*)((const char*)g_wt_hi + (size_t)n * 1024 + q * 8);
        pbl[j] = *(const uint2*)((const char*)g_wt_lo + (size_t)n * 1024 + q * 8);
    }

    // ---- store chunk 0 to smem ----
#pragma unroll
    for (int j = 0; j < 4; j++) {
        int idx = tid + j * 256;
        int r = idx >> 3, f4 = idx & 7;
        float4 v = pa[j];
        __nv_bfloat162 h01 = __floats2bfloat162_rn(v.x, v.y);
        __nv_bfloat162 h23 = __floats2bfloat162_rn(v.z, v.w);
        __nv_bfloat162 l01 = __floats2bfloat162_rn(
            v.x - __bfloat162float(__low2bfloat16(h01)),
            v.y - __bfloat162float(__high2bfloat16(h01)));
        __nv_bfloat162 l23 = __floats2bfloat162_rn(
            v.z - __bfloat162float(__low2bfloat16(h23)),
            v.w - __bfloat162float(__high2bfloat16(h23)));
        uint2 hw, lw;
        hw.x = *(uint32_t*)&h01; hw.y = *(uint32_t*)&h23;
        lw.x = *(uint32_t*)&l01; lw.y = *(uint32_t*)&l23;
        *(uint2*)(smem + A_HI + r * 80 + f4 * 8) = hw;
        *(uint2*)(smem + A_LO + r * 80 + f4 * 8) = lw;
    }
#pragma unroll
    for (int j = 0; j < 5; j++) {
        int idx = tid + j * 256;
        int n = idx >> 3, q = idx & 7;
        *(uint2*)(smem + B_HI + n * 80 + q * 8) = pbh[j];
        *(uint2*)(smem + B_LO + n * 80 + q * 8) = pbl[j];
    }
    __syncthreads();

#pragma unroll 1
    for (int c = 0; c < 16; c++) {
        // prefetch next chunk into registers (overlaps with compute below)
        if (c + 1 < 16) {
            int k0 = (c + 1) * 32;
#pragma unroll
            for (int j = 0; j < 4; j++) {
                int idx = tid + j * 256;
                int r = idx >> 3, f4 = idx & 7;
                pa[j] = make_float4(0.f, 0.f, 0.f, 0.f);
                if (bm + r < N_NODES)
                    pa[j] = *(const float4*)(x + (size_t)(bm + r) * F_IN + k0 + f4 * 4);
            }
#pragma unroll
            for (int j = 0; j < 5; j++) {
                int idx = tid + j * 256;
                int n = idx >> 3, q = idx & 7;
                pbh[j] = *(const uint2*)((const char*)g_wt_hi + (size_t)n * 1024 + k0 * 2 + q * 8);
                pbl[j] = *(const uint2*)((const char*)g_wt_lo + (size_t)n * 1024 + k0 * 2 + q * 8);
            }
        }

        // compute on current smem chunk: 2 k16 steps
#pragma unroll
        for (int kk = 0; kk < 2; kk++) {
            int kb = kk * 32;               // byte offset within 64B row chunk
            uint32_t afr[2][2][4];          // [mf][hi/lo][4]
#pragma unroll
            for (int mf = 0; mf < 2; mf++) {
                int r0 = wm * 32 + mf * 16 + g;
                int o0 = r0 * 80 + kb + tg * 4;
                int o1 = (r0 + 8) * 80 + kb + tg * 4;
                afr[mf][0][0] = *(const uint32_t*)(smem + A_HI + o0);
                afr[mf][0][1] = *(const uint32_t*)(smem + A_HI + o1);
                afr[mf][0][2] = *(const uint32_t*)(smem + A_HI + o0 + 16);
                afr[mf][0][3] = *(const uint32_t*)(smem + A_HI + o1 + 16);
                afr[mf][1][0] = *(const uint32_t*)(smem + A_LO + o0);
                afr[mf][1][1] = *(const uint32_t*)(smem + A_LO + o1);
                afr[mf][1][2] = *(const uint32_t*)(smem + A_LO + o0 + 16);
                afr[mf][1][3] = *(const uint32_t*)(smem + A_LO + o1 + 16);
            }
#pragma unroll
            for (int nf = 0; nf < 10; nf++) {
                int cl = wn * 80 + nf * 8 + g;
                int ob = cl * 80 + kb + tg * 4;
                uint32_t bh0 = *(const uint32_t*)(smem + B_HI + ob);
                uint32_t bh1 = *(const uint32_t*)(smem + B_HI + ob + 16);
                uint32_t bl0 = *(const uint32_t*)(smem + B_LO + ob);
                uint32_t bl1 = *(const uint32_t*)(smem + B_LO + ob + 16);
#pragma unroll
                for (int mf = 0; mf < 2; mf++) {
                    mma16816(acc[mf][nf], afr[mf][0], bh0, bh1);  // hi*hi
                    mma16816(acc[mf][nf], afr[mf][0], bl0, bl1);  // hi*lo
                    mma16816(acc[mf][nf], afr[mf][1], bh0, bh1);  // lo*hi
                }
            }
        }
        __syncthreads();

        if (c + 1 < 16) {
#pragma unroll
            for (int j = 0; j < 4; j++) {
                int idx = tid + j * 256;
                int r = idx >> 3, f4 = idx & 7;
                float4 v = pa[j];
                __nv_bfloat162 h01 = __floats2bfloat162_rn(v.x, v.y);
                __nv_bfloat162 h23 = __floats2bfloat162_rn(v.z, v.w);
                __nv_bfloat162 l01 = __floats2bfloat162_rn(
                    v.x - __bfloat162float(__low2bfloat16(h01)),
                    v.y - __bfloat162float(__high2bfloat16(h01)));
                __nv_bfloat162 l23 = __floats2bfloat162_rn(
                    v.z - __bfloat162float(__low2bfloat16(h23)),
                    v.w - __bfloat162float(__high2bfloat16(h23)));
                uint2 hw, lw;
                hw.x = *(uint32_t*)&h01; hw.y = *(uint32_t*)&h23;
                lw.x = *(uint32_t*)&l01; lw.y = *(uint32_t*)&l23;
                *(uint2*)(smem + A_HI + r * 80 + f4 * 8) = hw;
                *(uint2*)(smem + A_LO + r * 80 + f4 * 8) = lw;
            }
#pragma unroll
            for (int j = 0; j < 5; j++) {
                int idx = tid + j * 256;
                int n = idx >> 3, q = idx & 7;
                *(uint2*)(smem + B_HI + n * 80 + q * 8) = pbh[j];
                *(uint2*)(smem + B_LO + n * 80 + q * 8) = pbl[j];
            }
            __syncthreads();
        }
    }

    // ---- epilogue: accs -> smem Ds[128][164] -> coalesced g_h stores ----
    float* Ds = (float*)smem;
#pragma unroll
    for (int mf = 0; mf < 2; mf++) {
        int r = wm * 32 + mf * 16 + g;
#pragma unroll
        for (int nf = 0; nf < 10; nf++) {
            int cc = wn * 80 + nf * 8 + tg * 2;
            *(float2*)&Ds[r * 164 + cc]       = make_float2(acc[mf][nf][0], acc[mf][nf][1]);
            *(float2*)&Ds[(r + 8) * 164 + cc] = make_float2(acc[mf][nf][2], acc[mf][nf][3]);
        }
    }
    __syncthreads();

    int rows = N_NODES - bm;
    if (rows > 128) rows = 128;
    int total = rows * HID;
    for (int i = tid; i < total; i += 256) {
        int r = i / HID, cc = i - r * HID;
        g_h[(size_t)(bm + r) * HID + cc] = Ds[r * 164 + cc];
    }
}

// ---------------- Agg1 fused with relu + W2 projection ----------------------
__global__ void __launch_bounds__(256) k_agg1(const float* __restrict__ b1,
                                              const float* __restrict__ W2) {
    __shared__ float W2s[HID * N_CLS];
    __shared__ float b1s[HID];
    int tid = threadIdx.x;
    for (int i = tid; i < HID * N_CLS; i += 256) W2s[i] = W2[i];
    for (int i = tid; i < HID; i += 256) b1s[i] = b1[i];
    __syncthreads();

    int warp = tid >> 5, lane = tid & 31;
    int node = blockIdx.x * 8 + warp;
    if (node >= N_NODES) return;

    float acc[5] = {0.f, 0.f, 0.f, 0.f, 0.f};
    int beg = g_rowptr[node], end = g_rowptr[node + 1];
    for (int e = beg; e < end; e++) {
        int s = g_col[e];
        float ds = __ldg(&g_dis[s]);
        const float* hp = g_h + (size_t)s * HID;
#pragma unroll
        for (int m = 0; m < 5; m++) {
            int c = lane + 32 * m;
            if (c < HID) acc[m] = fmaf(ds, __ldg(hp + c), acc[m]);
        }
    }
    float di = g_dis[node];
    {
        const float* hp = g_h + (size_t)node * HID;
#pragma unroll
        for (int m = 0; m < 5; m++) {
            int c = lane + 32 * m;
            if (c < HID) acc[m] = fmaf(di, hp[c], acc[m]);
        }
    }
    float u[5];
#pragma unroll
    for (int m = 0; m < 5; m++) {
        int c = lane + 32 * m;
        u[m] = (c < HID) ? fmaxf(fmaf(di, acc[m], b1s[c]), 0.f) : 0.f;
    }

    float outk[N_CLS];
#pragma unroll
    for (int k = 0; k < N_CLS; k++) {
        float p = 0.f;
#pragma unroll
        for (int m = 0; m < 5; m++) {
            int c = lane + 32 * m;
            if (c < HID) p = fmaf(u[m], W2s[c * N_CLS + k], p);
        }
#pragma unroll
        for (int o = 16; o > 0; o >>= 1) p += __shfl_xor_sync(0xffffffffu, p, o);
        outk[k] = p;
    }
    if (lane == 0) {
#pragma unroll
        for (int k = 0; k < N_CLS; k++) g_h2[(size_t)node * N_CLS + k] = outk[k];
    }
}

// ---------------- Agg2 + bias + log_softmax ---------------------------------
__global__ void __launch_bounds__(256) k_agg2(const float* __restrict__ b2,
                                              float* __restrict__ out) {
    int i = blockIdx.x * blockDim.x + threadIdx.x;
    if (i >= N_NODES) return;

    float acc[N_CLS];
#pragma unroll
    for (int k = 0; k < N_CLS; k++) acc[k] = 0.f;

    int beg = g_rowptr[i], end = g_rowptr[i + 1];
    for (int e = beg; e < end; e++) {
        int s = g_col[e];
        float ds = __ldg(&g_dis[s]);
        const float* p = g_h2 + (size_t)s * N_CLS;
#pragma unroll
        for (int k = 0; k < N_CLS; k++) acc[k] = fmaf(ds, __ldg(p + k), acc[k]);
    }
    float di = g_dis[i];
    {
        const float* p = g_h2 + (size_t)i * N_CLS;
#pragma unroll
        for (int k = 0; k < N_CLS; k++) acc[k] = fmaf(di, p[k], acc[k]);
    }
    float v[N_CLS];
#pragma unroll
    for (int k = 0; k < N_CLS; k++) v[k] = fmaf(di, acc[k], __ldg(b2 + k));

    float m = v[0];
#pragma unroll
    for (int k = 1; k < N_CLS; k++) m = fmaxf(m, v[k]);
    float s = 0.f;
#pragma unroll
    for (int k = 0; k < N_CLS; k++) s += expf(v[k] - m);
    float lse = m + logf(s);
#pragma unroll
    for (int k = 0; k < N_CLS; k++) out[(size_t)i * N_CLS + k] = v[k] - lse;
}

// ---------------- launch -----------------------------------------------------
extern "C" void kernel_launch(void* const* d_in, const int* in_sizes, int n_in,
                              void* d_out, int out_size) {
    const float* x  = (const float*)d_in[0];
    const int*   ei = (const int*)d_in[1];
    const float* W1 = (const float*)d_in[2];
    const float* b1 = (const float*)d_in[3];
    const float* W2 = (const float*)d_in[4];
    const float* b2 = (const float*)d_in[5];
    float* out = (float*)d_out;

    const int* src = ei;
    const int* dst = ei + N_EDGES;

    cudaFuncSetAttribute(k_gemm_mma, cudaFuncAttributeMaxDynamicSharedMemorySize, SMEM_GEMM);

    k_prepw<<<(NPAD * F_IN + 255) / 256, 256>>>(W1);
    k_init_deg<<<(N_NODES + 255) / 256, 256>>>();
    k_count<<<(N_EDGES + 255) / 256, 256>>>(dst);
    k_scan1<<<SCAN_BLOCKS, 1024>>>();
    k_scan2<<<1, 1>>>();
    k_scan3<<<(N_NODES + 255) / 256, 256>>>();
    k_fill<<<(N_EDGES + 255) / 256, 256>>>(src, dst);

    k_gemm_mma<<<(N_NODES + 127) / 128, 256, SMEM_GEMM>>>(x);
    k_agg1<<<(N_NODES + 7) / 8, 256>>>(b1, W2);
    k_agg2<<<(N_NODES + 255) / 256, 256>>>(b2, out);
}

// round 6
// speedup vs baseline: 2.2568x; 1.1148x over previous
#include <cuda_runtime.h>
#include <cuda_bf16.h>
#include <cuda_fp16.h>
#include <math.h>
#include <stdint.h>

#define N_NODES 100000
#define N_EDGES 1600000
#define F_IN 512
#define HID 156
#define N_CLS 7
#define NPAD 160
#define NP2 80          // half2 pairs per row

// ---------------- scratch (device globals; no allocation allowed) ----------
__device__ __align__(16) __half g_h16[(size_t)N_NODES * NPAD];   // 32 MB, dis-scaled
__device__ __align__(16) float g_h2[(size_t)N_NODES * N_CLS];    // 2.8 MB, dis-scaled
__device__ float g_dis[N_NODES];
__device__ int   g_deg[N_NODES];
__device__ int   g_rowptr[N_NODES + 1];
__device__ int   g_cursor[N_NODES];
__device__ int   g_col[N_EDGES];
__device__ int   g_blocksums[128];
__device__ __align__(16) __nv_bfloat16 g_wt_hi[NPAD * F_IN];   // W1^T hi, [160][512]
__device__ __align__(16) __nv_bfloat16 g_wt_lo[NPAD * F_IN];   // W1^T lo

#define SCAN_BLOCKS ((N_NODES + 1023) / 1024)    // 98

// ---------------- degree / CSR build ---------------------------------------
__global__ void k_init_deg() {
    int i = blockIdx.x * blockDim.x + threadIdx.x;
    if (i < N_NODES) g_deg[i] = 1;
}
__global__ void k_count(const int* __restrict__ dst) {
    int e = blockIdx.x * blockDim.x + threadIdx.x;
    if (e < N_EDGES) atomicAdd(&g_deg[dst[e]], 1);
}
__global__ void k_scan1() {
    __shared__ int sh[1024];
    int t = threadIdx.x;
    int i = blockIdx.x * 1024 + t;
    int v = (i < N_NODES) ? (g_deg[i] - 1) : 0;
    sh[t] = v;
    __syncthreads();
    for (int off = 1; off < 1024; off <<= 1) {
        int add = (t >= off) ? sh[t - off] : 0;
        __syncthreads();
        sh[t] += add;
        __syncthreads();
    }
    int incl = sh[t];
    if (i < N_NODES) g_rowptr[i] = incl - v;
    if (t == 1023) g_blocksums[blockIdx.x] = incl;
}
__global__ void k_scan2() {
    int s = 0;
    for (int b = 0; b < SCAN_BLOCKS; b++) {
        int t = g_blocksums[b];
        g_blocksums[b] = s;
        s += t;
    }
}
__global__ void k_scan3() {
    int i = blockIdx.x * blockDim.x + threadIdx.x;
    if (i < N_NODES) {
        int r = g_rowptr[i] + g_blocksums[i >> 10];
        g_rowptr[i] = r;
        g_cursor[i] = r;
        g_dis[i] = rsqrtf((float)g_deg[i]);
        if (i == 0) g_rowptr[N_NODES] = N_EDGES;
    }
}
__global__ void k_fill(const int* __restrict__ src, const int* __restrict__ dst) {
    int e = blockIdx.x * blockDim.x + threadIdx.x;
    if (e < N_EDGES) {
        int d = dst[e];
        int pos = atomicAdd(&g_cursor[d], 1);
        g_col[pos] = src[e];
    }
}

// ---------------- W1 transpose + bf16 hi/lo split: g_wt[n][k] ---------------
__global__ void k_prepw(const float* __restrict__ W1) {
    int idx = blockIdx.x * 256 + threadIdx.x;
    if (idx >= NPAD * F_IN) return;
    int n = idx >> 9;
    int k = idx & 511;
    float v = (n < HID) ? W1[(size_t)k * HID + n] : 0.f;
    __nv_bfloat16 hi = __float2bfloat16(v);
    __nv_bfloat16 lo = __float2bfloat16(v - __bfloat162float(hi));
    g_wt_hi[idx] = hi;
    g_wt_lo[idx] = lo;
}

// ---------------- GEMM1 via mma.sync bf16-split -----------------------------
// CTA: 128(M) x 160(N) x 512(K). 8 warps = 4(M) x 2(N). hi*hi + hi*lo + lo*hi.
// Epilogue: scale by dis[row], convert to half2, stage in smem, uint4 stores.
#define A_HI 0
#define A_LO 10240
#define B_HI 20480
#define B_LO 33280
#define SMEM_GEMM 46080

__device__ __forceinline__ void mma16816(float* d, const uint32_t* a,
                                         uint32_t b0, uint32_t b1) {
    asm volatile(
        "mma.sync.aligned.m16n8k16.row.col.f32.bf16.bf16.f32 "
        "{%0,%1,%2,%3}, {%4,%5,%6,%7}, {%8,%9}, {%0,%1,%2,%3};"
        : "+f"(d[0]), "+f"(d[1]), "+f"(d[2]), "+f"(d[3])
        : "r"(a[0]), "r"(a[1]), "r"(a[2]), "r"(a[3]), "r"(b0), "r"(b1));
}

__global__ void __launch_bounds__(256) k_gemm_mma(const float* __restrict__ x) {
    extern __shared__ char smem[];
    int tid = threadIdx.x, wid = tid >> 5, lane = tid & 31;
    int g = lane >> 2, tg = lane & 3;
    int wm = wid & 3, wn = wid >> 2;
    int bm = blockIdx.x * 128;

    float acc[2][10][4];
#pragma unroll
    for (int i = 0; i < 2; i++)
#pragma unroll
        for (int j = 0; j < 10; j++)
#pragma unroll
            for (int q = 0; q < 4; q++) acc[i][j][q] = 0.f;

    float4 pa[4];
    uint2  pbh[5], pbl[5];

#pragma unroll
    for (int j = 0; j < 4; j++) {
        int idx = tid + j * 256;
        int r = idx >> 3, f4 = idx & 7;
        pa[j] = make_float4(0.f, 0.f, 0.f, 0.f);
        if (bm + r < N_NODES)
            pa[j] = *(const float4*)(x + (size_t)(bm + r) * F_IN + f4 * 4);
    }
#pragma unroll
    for (int j = 0; j < 5; j++) {
        int idx = tid + j * 256;
        int n = idx >> 3, q = idx & 7;
        pbh[j] = *(const uint2*)((const char*)g_wt_hi + (size_t)n * 1024 + q * 8);
        pbl[j] = *(const uint2*)((const char*)g_wt_lo + (size_t)n * 1024 + q * 8);
    }

#pragma unroll
    for (int j = 0; j < 4; j++) {
        int idx = tid + j * 256;
        int r = idx >> 3, f4 = idx & 7;
        float4 v = pa[j];
        __nv_bfloat162 h01 = __floats2bfloat162_rn(v.x, v.y);
        __nv_bfloat162 h23 = __floats2bfloat162_rn(v.z, v.w);
        __nv_bfloat162 l01 = __floats2bfloat162_rn(
            v.x - __bfloat162float(__low2bfloat16(h01)),
            v.y - __bfloat162float(__high2bfloat16(h01)));
        __nv_bfloat162 l23 = __floats2bfloat162_rn(
            v.z - __bfloat162float(__low2bfloat16(h23)),
            v.w - __bfloat162float(__high2bfloat16(h23)));
        uint2 hw, lw;
        hw.x = *(uint32_t*)&h01; hw.y = *(uint32_t*)&h23;
        lw.x = *(uint32_t*)&l01; lw.y = *(uint32_t*)&l23;
        *(uint2*)(smem + A_HI + r * 80 + f4 * 8) = hw;
        *(uint2*)(smem + A_LO + r * 80 + f4 * 8) = lw;
    }
#pragma unroll
    for (int j = 0; j < 5; j++) {
        int idx = tid + j * 256;
        int n = idx >> 3, q = idx & 7;
        *(uint2*)(smem + B_HI + n * 80 + q * 8) = pbh[j];
        *(uint2*)(smem + B_LO + n * 80 + q * 8) = pbl[j];
    }
    __syncthreads();

#pragma unroll 1
    for (int c = 0; c < 16; c++) {
        if (c + 1 < 16) {
            int k0 = (c + 1) * 32;
#pragma unroll
            for (int j = 0; j < 4; j++) {
                int idx = tid + j * 256;
                int r = idx >> 3, f4 = idx & 7;
                pa[j] = make_float4(0.f, 0.f, 0.f, 0.f);
                if (bm + r < N_NODES)
                    pa[j] = *(const float4*)(x + (size_t)(bm + r) * F_IN + k0 + f4 * 4);
            }
#pragma unroll
            for (int j = 0; j < 5; j++) {
                int idx = tid + j * 256;
                int n = idx >> 3, q = idx & 7;
                pbh[j] = *(const uint2*)((const char*)g_wt_hi + (size_t)n * 1024 + k0 * 2 + q * 8);
                pbl[j] = *(const uint2*)((const char*)g_wt_lo + (size_t)n * 1024 + k0 * 2 + q * 8);
            }
        }

#pragma unroll
        for (int kk = 0; kk < 2; kk++) {
            int kb = kk * 32;
            uint32_t afr[2][2][4];
#pragma unroll
            for (int mf = 0; mf < 2; mf++) {
                int r0 = wm * 32 + mf * 16 + g;
                int o0 = r0 * 80 + kb + tg * 4;
                int o1 = (r0 + 8) * 80 + kb + tg * 4;
                afr[mf][0][0] = *(const uint32_t*)(smem + A_HI + o0);
                afr[mf][0][1] = *(const uint32_t*)(smem + A_HI + o1);
                afr[mf][0][2] = *(const uint32_t*)(smem + A_HI + o0 + 16);
                afr[mf][0][3] = *(const uint32_t*)(smem + A_HI + o1 + 16);
                afr[mf][1][0] = *(const uint32_t*)(smem + A_LO + o0);
                afr[mf][1][1] = *(const uint32_t*)(smem + A_LO + o1);
                afr[mf][1][2] = *(const uint32_t*)(smem + A_LO + o0 + 16);
                afr[mf][1][3] = *(const uint32_t*)(smem + A_LO + o1 + 16);
            }
#pragma unroll
            for (int nf = 0; nf < 10; nf++) {
                int cl = wn * 80 + nf * 8 + g;
                int ob = cl * 80 + kb + tg * 4;
                uint32_t bh0 = *(const uint32_t*)(smem + B_HI + ob);
                uint32_t bh1 = *(const uint32_t*)(smem + B_HI + ob + 16);
                uint32_t bl0 = *(const uint32_t*)(smem + B_LO + ob);
                uint32_t bl1 = *(const uint32_t*)(smem + B_LO + ob + 16);
#pragma unroll
                for (int mf = 0; mf < 2; mf++) {
                    mma16816(acc[mf][nf], afr[mf][0], bh0, bh1);
                    mma16816(acc[mf][nf], afr[mf][0], bl0, bl1);
                    mma16816(acc[mf][nf], afr[mf][1], bh0, bh1);
                }
            }
        }
        __syncthreads();

        if (c + 1 < 16) {
#pragma unroll
            for (int j = 0; j < 4; j++) {
                int idx = tid + j * 256;
                int r = idx >> 3, f4 = idx & 7;
                float4 v = pa[j];
                __nv_bfloat162 h01 = __floats2bfloat162_rn(v.x, v.y);
                __nv_bfloat162 h23 = __floats2bfloat162_rn(v.z, v.w);
                __nv_bfloat162 l01 = __floats2bfloat162_rn(
                    v.x - __bfloat162float(__low2bfloat16(h01)),
                    v.y - __bfloat162float(__high2bfloat16(h01)));
                __nv_bfloat162 l23 = __floats2bfloat162_rn(
                    v.z - __bfloat162float(__low2bfloat16(h23)),
                    v.w - __bfloat162float(__high2bfloat16(h23)));
                uint2 hw, lw;
                hw.x = *(uint32_t*)&h01; hw.y = *(uint32_t*)&h23;
                lw.x = *(uint32_t*)&l01; lw.y = *(uint32_t*)&l23;
                *(uint2*)(smem + A_HI + r * 80 + f4 * 8) = hw;
                *(uint2*)(smem + A_LO + r * 80 + f4 * 8) = lw;
            }
#pragma unroll
            for (int j = 0; j < 5; j++) {
                int idx = tid + j * 256;
                int n = idx >> 3, q = idx & 7;
                *(uint2*)(smem + B_HI + n * 80 + q * 8) = pbh[j];
                *(uint2*)(smem + B_LO + n * 80 + q * 8) = pbl[j];
            }
            __syncthreads();
        }
    }

    // ---- epilogue: scale by dis, half2 pack -> smem Hs[128][84] u32 -> uint4
    uint32_t* Hs = (uint32_t*)smem;
#pragma unroll
    for (int mf = 0; mf < 2; mf++) {
        int r = wm * 32 + mf * 16 + g;
        float d0 = (bm + r < N_NODES) ? g_dis[bm + r] : 0.f;
        float d8 = (bm + r + 8 < N_NODES) ? g_dis[bm + r + 8] : 0.f;
#pragma unroll
        for (int nf = 0; nf < 10; nf++) {
            int p = wn * 40 + nf * 4 + tg;   // pair index
            __half2 v0 = __floats2half2_rn(acc[mf][nf][0] * d0, acc[mf][nf][1] * d0);
            __half2 v8 = __floats2half2_rn(acc[mf][nf][2] * d8, acc[mf][nf][3] * d8);
            Hs[r * 84 + p]       = *(uint32_t*)&v0;
            Hs[(r + 8) * 84 + p] = *(uint32_t*)&v8;
        }
    }
    __syncthreads();

    int rows = N_NODES - bm;
    if (rows > 128) rows = 128;
    int total4 = rows * 20;                  // 20 uint4 per row (80 u32)
    for (int i = tid; i < total4; i += 256) {
        int r = i / 20, q = i - r * 20;
        uint4 v = *(uint4*)&Hs[r * 84 + q * 4];
        *(uint4*)((char*)g_h16 + (size_t)(bm + r) * 320 + q * 16) = v;
    }
}

// ---------------- Agg1: gather dis-scaled h (fp16) + relu + W2 projection ---
__global__ void __launch_bounds__(256) k_agg1(const float* __restrict__ b1,
                                              const float* __restrict__ W2) {
    __shared__ float2 W2p[96 * N_CLS];   // [pair][k] rows 2p,2p+1 (zero padded)
    __shared__ float2 b1p[96];
    int tid = threadIdx.x;
    for (int i = tid; i < 96 * N_CLS; i += 256) {
        int p = i / N_CLS, k = i - p * N_CLS;
        float lo = (2 * p < HID) ? W2[(2 * p) * N_CLS + k] : 0.f;
        float hi = (2 * p + 1 < HID) ? W2[(2 * p + 1) * N_CLS + k] : 0.f;
        W2p[i] = make_float2(lo, hi);
    }
    for (int p = tid; p < 96; p += 256) {
        float lo = (2 * p < HID) ? b1[2 * p] : 0.f;
        float hi = (2 * p + 1 < HID) ? b1[2 * p + 1] : 0.f;
        b1p[p] = make_float2(lo, hi);
    }
    __syncthreads();

    int warp = tid >> 5, lane = tid & 31;
    int node = blockIdx.x * 8 + warp;
    if (node >= N_NODES) return;

    float2 a0 = make_float2(0.f, 0.f), a1 = a0, a2 = a0;
    int beg = g_rowptr[node], end = g_rowptr[node + 1];
    for (int e = beg; e < end; e++) {
        int s = g_col[e];
        const uint32_t* hp = (const uint32_t*)g_h16 + (size_t)s * NP2;
        uint32_t w0 = __ldg(hp + lane);
        uint32_t w1 = __ldg(hp + lane + 32);
        uint32_t w2 = (lane < 16) ? __ldg(hp + lane + 64) : 0u;
        float2 f0 = __half22float2(*(__half2*)&w0);
        float2 f1 = __half22float2(*(__half2*)&w1);
        float2 f2 = __half22float2(*(__half2*)&w2);
        a0.x += f0.x; a0.y += f0.y;
        a1.x += f1.x; a1.y += f1.y;
        a2.x += f2.x; a2.y += f2.y;
    }
    {   // self term (row already dis-scaled)
        const uint32_t* hp = (const uint32_t*)g_h16 + (size_t)node * NP2;
        uint32_t w0 = hp[lane];
        uint32_t w1 = hp[lane + 32];
        uint32_t w2 = (lane < 16) ? hp[lane + 64] : 0u;
        float2 f0 = __half22float2(*(__half2*)&w0);
        float2 f1 = __half22float2(*(__half2*)&w1);
        float2 f2 = __half22float2(*(__half2*)&w2);
        a0.x += f0.x; a0.y += f0.y;
        a1.x += f1.x; a1.y += f1.y;
        a2.x += f2.x; a2.y += f2.y;
    }
    float di = g_dis[node];
    float2 bb0 = b1p[lane], bb1 = b1p[lane + 32], bb2 = b1p[lane + 64];
    float2 u0 = make_float2(fmaxf(fmaf(di, a0.x, bb0.x), 0.f),
                            fmaxf(fmaf(di, a0.y, bb0.y), 0.f));
    float2 u1 = make_float2(fmaxf(fmaf(di, a1.x, bb1.x), 0.f),
                            fmaxf(fmaf(di, a1.y, bb1.y), 0.f));
    float2 u2 = make_float2(fmaxf(fmaf(di, a2.x, bb2.x), 0.f),
                            fmaxf(fmaf(di, a2.y, bb2.y), 0.f));
    if (lane >= 16) { u2.x = 0.f; u2.y = 0.f; }

    float outk[N_CLS];
#pragma unroll
    for (int k = 0; k < N_CLS; k++) {
        float2 w0 = W2p[lane * N_CLS + k];
        float2 w1 = W2p[(lane + 32) * N_CLS + k];
        float2 w2 = W2p[(lane + 64) * N_CLS + k];
        float p = u0.x * w0.x + u0.y * w0.y
                + u1.x * w1.x + u1.y * w1.y
                + u2.x * w2.x + u2.y * w2.y;
#pragma unroll
        for (int o = 16; o > 0; o >>= 1) p += __shfl_xor_sync(0xffffffffu, p, o);
        outk[k] = p;
    }
    if (lane == 0) {
#pragma unroll
        for (int k = 0; k < N_CLS; k++)
            g_h2[(size_t)node * N_CLS + k] = di * outk[k];   // dis-scaled
    }
}

// ---------------- Agg2 + bias + log_softmax ---------------------------------
__global__ void __launch_bounds__(256) k_agg2(const float* __restrict__ b2,
                                              float* __restrict__ out) {
    int i = blockIdx.x * blockDim.x + threadIdx.x;
    if (i >= N_NODES) return;

    float acc[N_CLS];
#pragma unroll
    for (int k = 0; k < N_CLS; k++) acc[k] = 0.f;

    int beg = g_rowptr[i], end = g_rowptr[i + 1];
    for (int e = beg; e < end; e++) {
        int s = g_col[e];
        const float* p = g_h2 + (size_t)s * N_CLS;
#pragma unroll
        for (int k = 0; k < N_CLS; k++) acc[k] += __ldg(p + k);
    }
    {
        const float* p = g_h2 + (size_t)i * N_CLS;
#pragma unroll
        for (int k = 0; k < N_CLS; k++) acc[k] += p[k];
    }
    float di = g_dis[i];
    float v[N_CLS];
#pragma unroll
    for (int k = 0; k < N_CLS; k++) v[k] = fmaf(di, acc[k], __ldg(b2 + k));

    float m = v[0];
#pragma unroll
    for (int k = 1; k < N_CLS; k++) m = fmaxf(m, v[k]);
    float s = 0.f;
#pragma unroll
    for (int k = 0; k < N_CLS; k++) s += expf(v[k] - m);
    float lse = m + logf(s);
#pragma unroll
    for (int k = 0; k < N_CLS; k++) out[(size_t)i * N_CLS + k] = v[k] - lse;
}

// ---------------- launch -----------------------------------------------------
extern "C" void kernel_launch(void* const* d_in, const int* in_sizes, int n_in,
                              void* d_out, int out_size) {
    const float* x  = (const float*)d_in[0];
    const int*   ei = (const int*)d_in[1];
    const float* W1 = (const float*)d_in[2];
    const float* b1 = (const float*)d_in[3];
    const float* W2 = (const float*)d_in[4];
    const float* b2 = (const float*)d_in[5];
    float* out = (float*)d_out;

    const int* src = ei;
    const int* dst = ei + N_EDGES;

    cudaFuncSetAttribute(k_gemm_mma, cudaFuncAttributeMaxDynamicSharedMemorySize, SMEM_GEMM);

    k_prepw<<<(NPAD * F_IN + 255) / 256, 256>>>(W1);
    k_init_deg<<<(N_NODES + 255) / 256, 256>>>();
    k_count<<<(N_EDGES + 255) / 256, 256>>>(dst);
    k_scan1<<<SCAN_BLOCKS, 1024>>>();
    k_scan2<<<1, 1>>>();
    k_scan3<<<(N_NODES + 255) / 256, 256>>>();
    k_fill<<<(N_EDGES + 255) / 256, 256>>>(src, dst);

    k_gemm_mma<<<(N_NODES + 127) / 128, 256, SMEM_GEMM>>>(x);
    k_agg1<<<(N_NODES + 7) / 8, 256>>>(b1, W2);
    k_agg2<<<(N_NODES + 255) / 256, 256>>>(b2, out);
}

// round 7
// speedup vs baseline: 2.3223x; 1.0290x over previous
#include <cuda_runtime.h>
#include <cuda_bf16.h>
#include <cuda_fp16.h>
#include <math.h>
#include <stdint.h>

#define N_NODES 100000
#define N_EDGES 1600000
#define F_IN 512
#define HID 156
#define N_CLS 7
#define NPAD 160
#define NP2 80          // half2 pairs per row
#define H2W 8           // padded row width of g_h2

// ---------------- scratch (device globals; no allocation allowed) ----------
__device__ __align__(16) __half g_h16[(size_t)N_NODES * NPAD];   // 32 MB, dis-scaled
__device__ __align__(16) float g_h2[(size_t)N_NODES * H2W];      // 3.2 MB, dis-scaled
__device__ float g_dis[N_NODES];
__device__ int   g_deg[N_NODES];
__device__ int   g_rowptr[N_NODES + 1];
__device__ int   g_cursor[N_NODES];
__device__ int   g_col[N_EDGES];
__device__ int   g_blocksums[128];
__device__ __align__(16) __nv_bfloat16 g_wt_hi[NPAD * F_IN];   // W1^T hi, [160][512]
__device__ __align__(16) __nv_bfloat16 g_wt_lo[NPAD * F_IN];   // W1^T lo

#define SCAN_BLOCKS ((N_NODES + 1023) / 1024)    // 98

// ---------------- degree / CSR build ---------------------------------------
__global__ void k_init_deg() {
    int i = blockIdx.x * blockDim.x + threadIdx.x;
    if (i < N_NODES) g_deg[i] = 1;
}
__global__ void k_count(const int* __restrict__ dst) {
    int e = blockIdx.x * blockDim.x + threadIdx.x;
    if (e < N_EDGES) atomicAdd(&g_deg[dst[e]], 1);
}
__global__ void k_scan1() {
    __shared__ int sh[1024];
    int t = threadIdx.x;
    int i = blockIdx.x * 1024 + t;
    int v = (i < N_NODES) ? (g_deg[i] - 1) : 0;
    sh[t] = v;
    __syncthreads();
    for (int off = 1; off < 1024; off <<= 1) {
        int add = (t >= off) ? sh[t - off] : 0;
        __syncthreads();
        sh[t] += add;
        __syncthreads();
    }
    int incl = sh[t];
    if (i < N_NODES) g_rowptr[i] = incl - v;      // exclusive within block
    if (t == 1023) g_blocksums[blockIdx.x] = incl;
}
// merged scan2+scan3: each block derives its own prefix of blocksums
__global__ void k_scan3m() {
    __shared__ int base_sh;
    int t = threadIdx.x;
    int i = blockIdx.x * 1024 + t;
    if (t == 0) {
        int s = 0;
        int b = blockIdx.x;
        for (int j = 0; j < b; j++) s += g_blocksums[j];
        base_sh = s;
    }
    __syncthreads();
    if (i < N_NODES) {
        int r = g_rowptr[i] + base_sh;
        g_rowptr[i] = r;
        g_cursor[i] = r;
        g_dis[i] = rsqrtf((float)g_deg[i]);
        if (i == 0) g_rowptr[N_NODES] = N_EDGES;
    }
}
__global__ void k_fill(const int* __restrict__ src, const int* __restrict__ dst) {
    int e = blockIdx.x * blockDim.x + threadIdx.x;
    if (e < N_EDGES) {
        int d = dst[e];
        int pos = atomicAdd(&g_cursor[d], 1);
        g_col[pos] = src[e];
    }
}

// ---------------- W1 transpose + bf16 hi/lo split: g_wt[n][k] ---------------
__global__ void k_prepw(const float* __restrict__ W1) {
    int idx = blockIdx.x * 256 + threadIdx.x;
    if (idx >= NPAD * F_IN) return;
    int n = idx >> 9;
    int k = idx & 511;
    float v = (n < HID) ? W1[(size_t)k * HID + n] : 0.f;
    __nv_bfloat16 hi = __float2bfloat16(v);
    __nv_bfloat16 lo = __float2bfloat16(v - __bfloat162float(hi));
    g_wt_hi[idx] = hi;
    g_wt_lo[idx] = lo;
}

// ---------------- GEMM1 via mma.sync bf16-split -----------------------------
// CTA: 128(M) x 160(N) x 512(K). 8 warps = 4(M) x 2(N). hi*hi + hi*lo + lo*hi.
// Epilogue: scale by dis[row], convert to half2, stage in smem, uint4 stores.
#define A_HI 0
#define A_LO 10240
#define B_HI 20480
#define B_LO 33280
#define SMEM_GEMM 46080

__device__ __forceinline__ void mma16816(float* d, const uint32_t* a,
                                         uint32_t b0, uint32_t b1) {
    asm volatile(
        "mma.sync.aligned.m16n8k16.row.col.f32.bf16.bf16.f32 "
        "{%0,%1,%2,%3}, {%4,%5,%6,%7}, {%8,%9}, {%0,%1,%2,%3};"
        : "+f"(d[0]), "+f"(d[1]), "+f"(d[2]), "+f"(d[3])
        : "r"(a[0]), "r"(a[1]), "r"(a[2]), "r"(a[3]), "r"(b0), "r"(b1));
}

__global__ void __launch_bounds__(256) k_gemm_mma(const float* __restrict__ x) {
    extern __shared__ char smem[];
    int tid = threadIdx.x, wid = tid >> 5, lane = tid & 31;
    int g = lane >> 2, tg = lane & 3;
    int wm = wid & 3, wn = wid >> 2;
    int bm = blockIdx.x * 128;

    float acc[2][10][4];
#pragma unroll
    for (int i = 0; i < 2; i++)
#pragma unroll
        for (int j = 0; j < 10; j++)
#pragma unroll
            for (int q = 0; q < 4; q++) acc[i][j][q] = 0.f;

    float4 pa[4];
    uint2  pbh[5], pbl[5];

#pragma unroll
    for (int j = 0; j < 4; j++) {
        int idx = tid + j * 256;
        int r = idx >> 3, f4 = idx & 7;
        pa[j] = make_float4(0.f, 0.f, 0.f, 0.f);
        if (bm + r < N_NODES)
            pa[j] = *(const float4*)(x + (size_t)(bm + r) * F_IN + f4 * 4);
    }
#pragma unroll
    for (int j = 0; j < 5; j++) {
        int idx = tid + j * 256;
        int n = idx >> 3, q = idx & 7;
        pbh[j] = *(const uint2*)((const char*)g_wt_hi + (size_t)n * 1024 + q * 8);
        pbl[j] = *(const uint2*)((const char*)g_wt_lo + (size_t)n * 1024 + q * 8);
    }

#pragma unroll
    for (int j = 0; j < 4; j++) {
        int idx = tid + j * 256;
        int r = idx >> 3, f4 = idx & 7;
        float4 v = pa[j];
        __nv_bfloat162 h01 = __floats2bfloat162_rn(v.x, v.y);
        __nv_bfloat162 h23 = __floats2bfloat162_rn(v.z, v.w);
        __nv_bfloat162 l01 = __floats2bfloat162_rn(
            v.x - __bfloat162float(__low2bfloat16(h01)),
            v.y - __bfloat162float(__high2bfloat16(h01)));
        __nv_bfloat162 l23 = __floats2bfloat162_rn(
            v.z - __bfloat162float(__low2bfloat16(h23)),
            v.w - __bfloat162float(__high2bfloat16(h23)));
        uint2 hw, lw;
        hw.x = *(uint32_t*)&h01; hw.y = *(uint32_t*)&h23;
        lw.x = *(uint32_t*)&l01; lw.y = *(uint32_t*)&l23;
        *(uint2*)(smem + A_HI + r * 80 + f4 * 8) = hw;
        *(uint2*)(smem + A_LO + r * 80 + f4 * 8) = lw;
    }
#pragma unroll
    for (int j = 0; j < 5; j++) {
        int idx = tid + j * 256;
        int n = idx >> 3, q = idx & 7;
        *(uint2*)(smem + B_HI + n * 80 + q * 8) = pbh[j];
        *(uint2*)(smem + B_LO + n * 80 + q * 8) = pbl[j];
    }
    __syncthreads();

#pragma unroll 1
    for (int c = 0; c < 16; c++) {
        if (c + 1 < 16) {
            int k0 = (c + 1) * 32;
#pragma unroll
            for (int j = 0; j < 4; j++) {
                int idx = tid + j * 256;
                int r = idx >> 3, f4 = idx & 7;
                pa[j] = make_float4(0.f, 0.f, 0.f, 0.f);
                if (bm + r < N_NODES)
                    pa[j] = *(const float4*)(x + (size_t)(bm + r) * F_IN + k0 + f4 * 4);
            }
#pragma unroll
            for (int j = 0; j < 5; j++) {
                int idx = tid + j * 256;
                int n = idx >> 3, q = idx & 7;
                pbh[j] = *(const uint2*)((const char*)g_wt_hi + (size_t)n * 1024 + k0 * 2 + q * 8);
                pbl[j] = *(const uint2*)((const char*)g_wt_lo + (size_t)n * 1024 + k0 * 2 + q * 8);
            }
        }

#pragma unroll
        for (int kk = 0; kk < 2; kk++) {
            int kb = kk * 32;
            uint32_t afr[2][2][4];
#pragma unroll
            for (int mf = 0; mf < 2; mf++) {
                int r0 = wm * 32 + mf * 16 + g;
                int o0 = r0 * 80 + kb + tg * 4;
                int o1 = (r0 + 8) * 80 + kb + tg * 4;
                afr[mf][0][0] = *(const uint32_t*)(smem + A_HI + o0);
                afr[mf][0][1] = *(const uint32_t*)(smem + A_HI + o1);
                afr[mf][0][2] = *(const uint32_t*)(smem + A_HI + o0 + 16);
                afr[mf][0][3] = *(const uint32_t*)(smem + A_HI + o1 + 16);
                afr[mf][1][0] = *(const uint32_t*)(smem + A_LO + o0);
                afr[mf][1][1] = *(const uint32_t*)(smem + A_LO + o1);
                afr[mf][1][2] = *(const uint32_t*)(smem + A_LO + o0 + 16);
                afr[mf][1][3] = *(const uint32_t*)(smem + A_LO + o1 + 16);
            }
#pragma unroll
            for (int nf = 0; nf < 10; nf++) {
                int cl = wn * 80 + nf * 8 + g;
                int ob = cl * 80 + kb + tg * 4;
                uint32_t bh0 = *(const uint32_t*)(smem + B_HI + ob);
                uint32_t bh1 = *(const uint32_t*)(smem + B_HI + ob + 16);
                uint32_t bl0 = *(const uint32_t*)(smem + B_LO + ob);
                uint32_t bl1 = *(const uint32_t*)(smem + B_LO + ob + 16);
#pragma unroll
                for (int mf = 0; mf < 2; mf++) {
                    mma16816(acc[mf][nf], afr[mf][0], bh0, bh1);
                    mma16816(acc[mf][nf], afr[mf][0], bl0, bl1);
                    mma16816(acc[mf][nf], afr[mf][1], bh0, bh1);
                }
            }
        }
        __syncthreads();

        if (c + 1 < 16) {
#pragma unroll
            for (int j = 0; j < 4; j++) {
                int idx = tid + j * 256;
                int r = idx >> 3, f4 = idx & 7;
                float4 v = pa[j];
                __nv_bfloat162 h01 = __floats2bfloat162_rn(v.x, v.y);
                __nv_bfloat162 h23 = __floats2bfloat162_rn(v.z, v.w);
                __nv_bfloat162 l01 = __floats2bfloat162_rn(
                    v.x - __bfloat162float(__low2bfloat16(h01)),
                    v.y - __bfloat162float(__high2bfloat16(h01)));
                __nv_bfloat162 l23 = __floats2bfloat162_rn(
                    v.z - __bfloat162float(__low2bfloat16(h23)),
                    v.w - __bfloat162float(__high2bfloat16(h23)));
                uint2 hw, lw;
                hw.x = *(uint32_t*)&h01; hw.y = *(uint32_t*)&h23;
                lw.x = *(uint32_t*)&l01; lw.y = *(uint32_t*)&l23;
                *(uint2*)(smem + A_HI + r * 80 + f4 * 8) = hw;
                *(uint2*)(smem + A_LO + r * 80 + f4 * 8) = lw;
            }
#pragma unroll
            for (int j = 0; j < 5; j++) {
                int idx = tid + j * 256;
                int n = idx >> 3, q = idx & 7;
                *(uint2*)(smem + B_HI + n * 80 + q * 8) = pbh[j];
                *(uint2*)(smem + B_LO + n * 80 + q * 8) = pbl[j];
            }
            __syncthreads();
        }
    }

    // ---- epilogue: scale by dis, half2 pack -> smem Hs[128][84] u32 -> uint4
    uint32_t* Hs = (uint32_t*)smem;
#pragma unroll
    for (int mf = 0; mf < 2; mf++) {
        int r = wm * 32 + mf * 16 + g;
        float d0 = (bm + r < N_NODES) ? g_dis[bm + r] : 0.f;
        float d8 = (bm + r + 8 < N_NODES) ? g_dis[bm + r + 8] : 0.f;
#pragma unroll
        for (int nf = 0; nf < 10; nf++) {
            int p = wn * 40 + nf * 4 + tg;   // pair index
            __half2 v0 = __floats2half2_rn(acc[mf][nf][0] * d0, acc[mf][nf][1] * d0);
            __half2 v8 = __floats2half2_rn(acc[mf][nf][2] * d8, acc[mf][nf][3] * d8);
            Hs[r * 84 + p]       = *(uint32_t*)&v0;
            Hs[(r + 8) * 84 + p] = *(uint32_t*)&v8;
        }
    }
    __syncthreads();

    int rows = N_NODES - bm;
    if (rows > 128) rows = 128;
    int total4 = rows * 20;                  // 20 uint4 per row (80 u32)
    for (int i = tid; i < total4; i += 256) {
        int r = i / 20, q = i - r * 20;
        uint4 v = *(uint4*)&Hs[r * 84 + q * 4];
        *(uint4*)((char*)g_h16 + (size_t)(bm + r) * 320 + q * 16) = v;
    }
}

// ---------------- Agg1: gather dis-scaled h (fp16) + relu + W2 projection ---
__global__ void __launch_bounds__(256) k_agg1(const float* __restrict__ b1,
                                              const float* __restrict__ W2) {
    __shared__ float2 W2p[96 * N_CLS];   // [pair][k] rows 2p,2p+1 (zero padded)
    __shared__ float2 b1p[96];
    int tid = threadIdx.x;
    for (int i = tid; i < 96 * N_CLS; i += 256) {
        int p = i / N_CLS, k = i - p * N_CLS;
        float lo = (2 * p < HID) ? W2[(2 * p) * N_CLS + k] : 0.f;
        float hi = (2 * p + 1 < HID) ? W2[(2 * p + 1) * N_CLS + k] : 0.f;
        W2p[i] = make_float2(lo, hi);
    }
    for (int p = tid; p < 96; p += 256) {
        float lo = (2 * p < HID) ? b1[2 * p] : 0.f;
        float hi = (2 * p + 1 < HID) ? b1[2 * p + 1] : 0.f;
        b1p[p] = make_float2(lo, hi);
    }
    __syncthreads();

    int warp = tid >> 5, lane = tid & 31;
    int node = blockIdx.x * 8 + warp;
    if (node >= N_NODES) return;

    float2 a0 = make_float2(0.f, 0.f), a1 = a0, a2 = a0;
    int beg = g_rowptr[node], end = g_rowptr[node + 1];
    const uint32_t* __restrict__ hbase = (const uint32_t*)g_h16;
    const int* __restrict__ colp = g_col;
#pragma unroll 2
    for (int e = beg; e < end; e++) {
        int s = __ldg(colp + e);
        const uint32_t* hp = hbase + (size_t)s * NP2;
        uint32_t w0 = __ldg(hp + lane);
        uint32_t w1 = __ldg(hp + lane + 32);
        uint32_t w2 = (lane < 16) ? __ldg(hp + lane + 64) : 0u;
        float2 f0 = __half22float2(*(__half2*)&w0);
        float2 f1 = __half22float2(*(__half2*)&w1);
        float2 f2 = __half22float2(*(__half2*)&w2);
        a0.x += f0.x; a0.y += f0.y;
        a1.x += f1.x; a1.y += f1.y;
        a2.x += f2.x; a2.y += f2.y;
    }
    {   // self term (row already dis-scaled)
        const uint32_t* hp = hbase + (size_t)node * NP2;
        uint32_t w0 = hp[lane];
        uint32_t w1 = hp[lane + 32];
        uint32_t w2 = (lane < 16) ? hp[lane + 64] : 0u;
        float2 f0 = __half22float2(*(__half2*)&w0);
        float2 f1 = __half22float2(*(__half2*)&w1);
        float2 f2 = __half22float2(*(__half2*)&w2);
        a0.x += f0.x; a0.y += f0.y;
        a1.x += f1.x; a1.y += f1.y;
        a2.x += f2.x; a2.y += f2.y;
    }
    float di = g_dis[node];
    float2 bb0 = b1p[lane], bb1 = b1p[lane + 32], bb2 = b1p[lane + 64];
    float2 u0 = make_float2(fmaxf(fmaf(di, a0.x, bb0.x), 0.f),
                            fmaxf(fmaf(di, a0.y, bb0.y), 0.f));
    float2 u1 = make_float2(fmaxf(fmaf(di, a1.x, bb1.x), 0.f),
                            fmaxf(fmaf(di, a1.y, bb1.y), 0.f));
    float2 u2 = make_float2(fmaxf(fmaf(di, a2.x, bb2.x), 0.f),
                            fmaxf(fmaf(di, a2.y, bb2.y), 0.f));
    if (lane >= 16) { u2.x = 0.f; u2.y = 0.f; }

    float outk[N_CLS];
#pragma unroll
    for (int k = 0; k < N_CLS; k++) {
        float2 w0 = W2p[lane * N_CLS + k];
        float2 w1 = W2p[(lane + 32) * N_CLS + k];
        float2 w2 = W2p[(lane + 64) * N_CLS + k];
        float p = u0.x * w0.x + u0.y * w0.y
                + u1.x * w1.x + u1.y * w1.y
                + u2.x * w2.x + u2.y * w2.y;
#pragma unroll
        for (int o = 16; o > 0; o >>= 1) p += __shfl_xor_sync(0xffffffffu, p, o);
        outk[k] = p;
    }
    if (lane == 0) {
#pragma unroll
        for (int k = 0; k < N_CLS; k++)
            g_h2[(size_t)node * H2W + k] = di * outk[k];   // dis-scaled, padded row
    }
}

// ---------------- Agg2 + bias + log_softmax ---------------------------------
__global__ void __launch_bounds__(256) k_agg2(const float* __restrict__ b2,
                                              float* __restrict__ out) {
    int i = blockIdx.x * blockDim.x + threadIdx.x;
    if (i >= N_NODES) return;

    float a0 = 0.f, a1 = 0.f, a2 = 0.f, a3 = 0.f, a4 = 0.f, a5 = 0.f, a6 = 0.f;

    int beg = g_rowptr[i], end = g_rowptr[i + 1];
    const int* __restrict__ colp = g_col;
#pragma unroll 2
    for (int e = beg; e < end; e++) {
        int s = __ldg(colp + e);
        const float4* p = (const float4*)(g_h2 + (size_t)s * H2W);
        float4 A = __ldg(p);
        float4 B = __ldg(p + 1);
        a0 += A.x; a1 += A.y; a2 += A.z; a3 += A.w;
        a4 += B.x; a5 += B.y; a6 += B.z;
    }
    {
        const float4* p = (const float4*)(g_h2 + (size_t)i * H2W);
        float4 A = *p;
        float4 B = *(p + 1);
        a0 += A.x; a1 += A.y; a2 += A.z; a3 += A.w;
        a4 += B.x; a5 += B.y; a6 += B.z;
    }
    float di = g_dis[i];
    float v[N_CLS];
    v[0] = fmaf(di, a0, __ldg(b2 + 0));
    v[1] = fmaf(di, a1, __ldg(b2 + 1));
    v[2] = fmaf(di, a2, __ldg(b2 + 2));
    v[3] = fmaf(di, a3, __ldg(b2 + 3));
    v[4] = fmaf(di, a4, __ldg(b2 + 4));
    v[5] = fmaf(di, a5, __ldg(b2 + 5));
    v[6] = fmaf(di, a6, __ldg(b2 + 6));

    float m = v[0];
#pragma unroll
    for (int k = 1; k < N_CLS; k++) m = fmaxf(m, v[k]);
    float s = 0.f;
#pragma unroll
    for (int k = 0; k < N_CLS; k++) s += expf(v[k] - m);
    float lse = m + logf(s);
#pragma unroll
    for (int k = 0; k < N_CLS; k++) out[(size_t)i * N_CLS + k] = v[k] - lse;
}

// ---------------- launch -----------------------------------------------------
extern "C" void kernel_launch(void* const* d_in, const int* in_sizes, int n_in,
                              void* d_out, int out_size) {
    const float* x  = (const float*)d_in[0];
    const int*   ei = (const int*)d_in[1];
    const float* W1 = (const float*)d_in[2];
    const float* b1 = (const float*)d_in[3];
    const float* W2 = (const float*)d_in[4];
    const float* b2 = (const float*)d_in[5];
    float* out = (float*)d_out;

    const int* src = ei;
    const int* dst = ei + N_EDGES;

    cudaFuncSetAttribute(k_gemm_mma, cudaFuncAttributeMaxDynamicSharedMemorySize, SMEM_GEMM);

    // launch order chosen so k_gemm_mma is launch index 5 (ncu -s 5 -c 1)
    k_prepw<<<(NPAD * F_IN + 255) / 256, 256>>>(W1);               // 0
    k_init_deg<<<(N_NODES + 255) / 256, 256>>>();                  // 1
    k_count<<<(N_EDGES + 255) / 256, 256>>>(dst);                  // 2
    k_scan1<<<SCAN_BLOCKS, 1024>>>();                              // 3
    k_scan3m<<<SCAN_BLOCKS, 1024>>>();                             // 4
    k_gemm_mma<<<(N_NODES + 127) / 128, 256, SMEM_GEMM>>>(x);      // 5
    k_fill<<<(N_EDGES + 255) / 256, 256>>>(src, dst);              // 6
    k_agg1<<<(N_NODES + 7) / 8, 256>>>(b1, W2);                    // 7
    k_agg2<<<(N_NODES + 255) / 256, 256>>>(b2, out);               // 8
}

// round 8
// speedup vs baseline: 2.4540x; 1.0567x over previous
#include <cuda_runtime.h>
#include <cuda_bf16.h>
#include <cuda_fp16.h>
#include <math.h>
#include <stdint.h>

#define N_NODES 100000
#define N_EDGES 1600000
#define F_IN 512
#define HID 156
#define N_CLS 7
#define NPAD 160
#define NP2 80          // half2 pairs per row
#define H2W 8           // padded row width of g_h2

// ---------------- scratch (device globals; no allocation allowed) ----------
__device__ __align__(16) __half g_h16[(size_t)N_NODES * NPAD];   // 32 MB, dis-scaled
__device__ __align__(16) float g_h2[(size_t)N_NODES * H2W];      // 3.2 MB, dis-scaled
__device__ float g_dis[N_NODES];
__device__ int   g_deg[N_NODES];
__device__ int   g_rowptr[N_NODES + 1];
__device__ int   g_cursor[N_NODES];
__device__ int   g_col[N_EDGES];
__device__ int   g_blocksums[128];
__device__ __align__(16) __nv_bfloat16 g_wt_hi[NPAD * F_IN];   // W1^T hi, [160][512]
__device__ __align__(16) __nv_bfloat16 g_wt_lo[NPAD * F_IN];   // W1^T lo

#define SCAN_BLOCKS ((N_NODES + 1023) / 1024)    // 98

// ---------------- setup: W1 transpose/split + deg init (merged) -------------
__global__ void k_setup(const float* __restrict__ W1) {
    int idx = blockIdx.x * 256 + threadIdx.x;
    if (idx < NPAD * F_IN) {
        int n = idx >> 9;
        int k = idx & 511;
        float v = (n < HID) ? W1[(size_t)k * HID + n] : 0.f;
        __nv_bfloat16 hi = __float2bfloat16(v);
        __nv_bfloat16 lo = __float2bfloat16(v - __bfloat162float(hi));
        g_wt_hi[idx] = hi;
        g_wt_lo[idx] = lo;
    }
    if (idx < N_NODES) g_deg[idx] = 1;
}

// ---------------- degree / CSR build ---------------------------------------
__global__ void k_count(const int* __restrict__ dst) {
    int e = blockIdx.x * blockDim.x + threadIdx.x;
    if (e < N_EDGES) atomicAdd(&g_deg[dst[e]], 1);
}
__global__ void k_scan1() {
    __shared__ int sh[1024];
    int t = threadIdx.x;
    int i = blockIdx.x * 1024 + t;
    int v = (i < N_NODES) ? (g_deg[i] - 1) : 0;
    sh[t] = v;
    __syncthreads();
    for (int off = 1; off < 1024; off <<= 1) {
        int add = (t >= off) ? sh[t - off] : 0;
        __syncthreads();
        sh[t] += add;
        __syncthreads();
    }
    int incl = sh[t];
    if (i < N_NODES) g_rowptr[i] = incl - v;
    if (t == 1023) g_blocksums[blockIdx.x] = incl;
}
__global__ void k_scan3m() {
    __shared__ int base_sh;
    int t = threadIdx.x;
    int i = blockIdx.x * 1024 + t;
    if (t == 0) {
        int s = 0;
        int b = blockIdx.x;
        for (int j = 0; j < b; j++) s += g_blocksums[j];
        base_sh = s;
    }
    __syncthreads();
    if (i < N_NODES) {
        int r = g_rowptr[i] + base_sh;
        g_rowptr[i] = r;
        g_cursor[i] = r;
        g_dis[i] = rsqrtf((float)g_deg[i]);
        if (i == 0) g_rowptr[N_NODES] = N_EDGES;
    }
}
__global__ void k_fill(const int* __restrict__ src, const int* __restrict__ dst) {
    int e = blockIdx.x * blockDim.x + threadIdx.x;
    if (e < N_EDGES) {
        int d = dst[e];
        int pos = atomicAdd(&g_cursor[d], 1);
        g_col[pos] = src[e];
    }
}

// ---------------- GEMM1 via mma.sync bf16-split + ldmatrix ------------------
#define A_HI 0
#define A_LO 10240
#define B_HI 20480
#define B_LO 33280
#define SMEM_GEMM 46080

__device__ __forceinline__ void mma16816(float* d, const uint32_t* a,
                                         uint32_t b0, uint32_t b1) {
    asm volatile(
        "mma.sync.aligned.m16n8k16.row.col.f32.bf16.bf16.f32 "
        "{%0,%1,%2,%3}, {%4,%5,%6,%7}, {%8,%9}, {%0,%1,%2,%3};"
        : "+f"(d[0]), "+f"(d[1]), "+f"(d[2]), "+f"(d[3])
        : "r"(a[0]), "r"(a[1]), "r"(a[2]), "r"(a[3]), "r"(b0), "r"(b1));
}
#define LDSM4(r, addr) \
    asm volatile("ldmatrix.sync.aligned.m8n8.x4.shared.b16 {%0,%1,%2,%3}, [%4];" \
        : "=r"((r)[0]), "=r"((r)[1]), "=r"((r)[2]), "=r"((r)[3]) : "r"(addr))

__global__ void __launch_bounds__(256) k_gemm_mma(const float* __restrict__ x) {
    extern __shared__ char smem[];
    int tid = threadIdx.x, wid = tid >> 5, lane = tid & 31;
    int g = lane >> 2, tg = lane & 3;
    int wm = wid & 3, wn = wid >> 2;
    int bm = blockIdx.x * 128;

    uint32_t sbase = (uint32_t)__cvta_generic_to_shared(smem);
    // ldmatrix per-lane addresses (row stride 80B; phases bank-conflict-free)
    int l8 = lane & 7;
    int aRow = l8 + ((lane >> 3) & 1) * 8;
    int aCol = (lane >= 16) ? 16 : 0;
    uint32_t aHiAddr = sbase + A_HI + (uint32_t)(wm * 32 + aRow) * 80 + aCol;
    uint32_t aLoAddr = sbase + A_LO + (uint32_t)(wm * 32 + aRow) * 80 + aCol;
    int bRow = l8 + ((lane >> 4) & 1) * 8;
    int bCol = ((lane >> 3) & 1) * 16;
    uint32_t bHiAddr = sbase + B_HI + (uint32_t)(wn * 80 + bRow) * 80 + bCol;
    uint32_t bLoAddr = sbase + B_LO + (uint32_t)(wn * 80 + bRow) * 80 + bCol;

    float acc[2][10][4];
#pragma unroll
    for (int i = 0; i < 2; i++)
#pragma unroll
        for (int j = 0; j < 10; j++)
#pragma unroll
            for (int q = 0; q < 4; q++) acc[i][j][q] = 0.f;

    float4 pa[4];
    uint2  pbh[5], pbl[5];

#pragma unroll
    for (int j = 0; j < 4; j++) {
        int idx = tid + j * 256;
        int r = idx >> 3, f4 = idx & 7;
        pa[j] = make_float4(0.f, 0.f, 0.f, 0.f);
        if (bm + r < N_NODES)
            pa[j] = *(const float4*)(x + (size_t)(bm + r) * F_IN + f4 * 4);
    }
#pragma unroll
    for (int j = 0; j < 5; j++) {
        int idx = tid + j * 256;
        int n = idx >> 3, q = idx & 7;
        pbh[j] = *(const uint2*)((const char*)g_wt_hi + (size_t)n * 1024 + q * 8);
        pbl[j] = *(const uint2*)((const char*)g_wt_lo + (size_t)n * 1024 + q * 8);
    }

#pragma unroll
    for (int j = 0; j < 4; j++) {
        int idx = tid + j * 256;
        int r = idx >> 3, f4 = idx & 7;
        float4 v = pa[j];
        __nv_bfloat162 h01 = __floats2bfloat162_rn(v.x, v.y);
        __nv_bfloat162 h23 = __floats2bfloat162_rn(v.z, v.w);
        __nv_bfloat162 l01 = __floats2bfloat162_rn(
            v.x - __bfloat162float(__low2bfloat16(h01)),
            v.y - __bfloat162float(__high2bfloat16(h01)));
        __nv_bfloat162 l23 = __floats2bfloat162_rn(
            v.z - __bfloat162float(__low2bfloat16(h23)),
            v.w - __bfloat162float(__high2bfloat16(h23)));
        uint2 hw, lw;
        hw.x = *(uint32_t*)&h01; hw.y = *(uint32_t*)&h23;
        lw.x = *(uint32_t*)&l01; lw.y = *(uint32_t*)&l23;
        *(uint2*)(smem + A_HI + r * 80 + f4 * 8) = hw;
        *(uint2*)(smem + A_LO + r * 80 + f4 * 8) = lw;
    }
#pragma unroll
    for (int j = 0; j < 5; j++) {
        int idx = tid + j * 256;
        int n = idx >> 3, q = idx & 7;
        *(uint2*)(smem + B_HI + n * 80 + q * 8) = pbh[j];
        *(uint2*)(smem + B_LO + n * 80 + q * 8) = pbl[j];
    }
    __syncthreads();

#pragma unroll 1
    for (int c = 0; c < 16; c++) {
        if (c + 1 < 16) {
            int k0 = (c + 1) * 32;
#pragma unroll
            for (int j = 0; j < 4; j++) {
                int idx = tid + j * 256;
                int r = idx >> 3, f4 = idx & 7;
                pa[j] = make_float4(0.f, 0.f, 0.f, 0.f);
                if (bm + r < N_NODES)
                    pa[j] = *(const float4*)(x + (size_t)(bm + r) * F_IN + k0 + f4 * 4);
            }
#pragma unroll
            for (int j = 0; j < 5; j++) {
                int idx = tid + j * 256;
                int n = idx >> 3, q = idx & 7;
                pbh[j] = *(const uint2*)((const char*)g_wt_hi + (size_t)n * 1024 + k0 * 2 + q * 8);
                pbl[j] = *(const uint2*)((const char*)g_wt_lo + (size_t)n * 1024 + k0 * 2 + q * 8);
            }
        }

#pragma unroll
        for (int kk = 0; kk < 2; kk++) {
            int kb = kk * 32;
            uint32_t ah[2][4], al[2][4];
#pragma unroll
            for (int mf = 0; mf < 2; mf++) {
                LDSM4(ah[mf], aHiAddr + mf * 1280 + kb);
                LDSM4(al[mf], aLoAddr + mf * 1280 + kb);
            }
#pragma unroll
            for (int pnf = 0; pnf < 5; pnf++) {
                uint32_t bh[4], bl[4];
                LDSM4(bh, bHiAddr + pnf * 1280 + kb);
                LDSM4(bl, bLoAddr + pnf * 1280 + kb);
#pragma unroll
                for (int mf = 0; mf < 2; mf++) {
                    mma16816(acc[mf][2 * pnf],     ah[mf], bh[0], bh[1]);
                    mma16816(acc[mf][2 * pnf],     ah[mf], bl[0], bl[1]);
                    mma16816(acc[mf][2 * pnf],     al[mf], bh[0], bh[1]);
                    mma16816(acc[mf][2 * pnf + 1], ah[mf], bh[2], bh[3]);
                    mma16816(acc[mf][2 * pnf + 1], ah[mf], bl[2], bl[3]);
                    mma16816(acc[mf][2 * pnf + 1], al[mf], bh[2], bh[3]);
                }
            }
        }
        __syncthreads();

        if (c + 1 < 16) {
#pragma unroll
            for (int j = 0; j < 4; j++) {
                int idx = tid + j * 256;
                int r = idx >> 3, f4 = idx & 7;
                float4 v = pa[j];
                __nv_bfloat162 h01 = __floats2bfloat162_rn(v.x, v.y);
                __nv_bfloat162 h23 = __floats2bfloat162_rn(v.z, v.w);
                __nv_bfloat162 l01 = __floats2bfloat162_rn(
                    v.x - __bfloat162float(__low2bfloat16(h01)),
                    v.y - __bfloat162float(__high2bfloat16(h01)));
                __nv_bfloat162 l23 = __floats2bfloat162_rn(
                    v.z - __bfloat162float(__low2bfloat16(h23)),
                    v.w - __bfloat162float(__high2bfloat16(h23)));
                uint2 hw, lw;
                hw.x = *(uint32_t*)&h01; hw.y = *(uint32_t*)&h23;
                lw.x = *(uint32_t*)&l01; lw.y = *(uint32_t*)&l23;
                *(uint2*)(smem + A_HI + r * 80 + f4 * 8) = hw;
                *(uint2*)(smem + A_LO + r * 80 + f4 * 8) = lw;
            }
#pragma unroll
            for (int j = 0; j < 5; j++) {
                int idx = tid + j * 256;
                int n = idx >> 3, q = idx & 7;
                *(uint2*)(smem + B_HI + n * 80 + q * 8) = pbh[j];
                *(uint2*)(smem + B_LO + n * 80 + q * 8) = pbl[j];
            }
            __syncthreads();
        }
    }

    // ---- epilogue: scale by dis, half2 pack -> smem Hs[128][84] u32 -> uint4
    uint32_t* Hs = (uint32_t*)smem;
#pragma unroll
    for (int mf = 0; mf < 2; mf++) {
        int r = wm * 32 + mf * 16 + g;
        float d0 = (bm + r < N_NODES) ? g_dis[bm + r] : 0.f;
        float d8 = (bm + r + 8 < N_NODES) ? g_dis[bm + r + 8] : 0.f;
#pragma unroll
        for (int nf = 0; nf < 10; nf++) {
            int p = wn * 40 + nf * 4 + tg;
            __half2 v0 = __floats2half2_rn(acc[mf][nf][0] * d0, acc[mf][nf][1] * d0);
            __half2 v8 = __floats2half2_rn(acc[mf][nf][2] * d8, acc[mf][nf][3] * d8);
            Hs[r * 84 + p]       = *(uint32_t*)&v0;
            Hs[(r + 8) * 84 + p] = *(uint32_t*)&v8;
        }
    }
    __syncthreads();

    int rows = N_NODES - bm;
    if (rows > 128) rows = 128;
    int total4 = rows * 20;
    for (int i = tid; i < total4; i += 256) {
        int r = i / 20, q = i - r * 20;
        uint4 v = *(uint4*)&Hs[r * 84 + q * 4];
        *(uint4*)((char*)g_h16 + (size_t)(bm + r) * 320 + q * 16) = v;
    }
}

// ---------------- Agg1: gather dis-scaled h (fp16) + relu + W2 projection ---
__global__ void __launch_bounds__(256) k_agg1(const float* __restrict__ b1,
                                              const float* __restrict__ W2) {
    __shared__ float2 W2p[96 * N_CLS];
    __shared__ float2 b1p[96];
    int tid = threadIdx.x;
    for (int i = tid; i < 96 * N_CLS; i += 256) {
        int p = i / N_CLS, k = i - p * N_CLS;
        float lo = (2 * p < HID) ? W2[(2 * p) * N_CLS + k] : 0.f;
        float hi = (2 * p + 1 < HID) ? W2[(2 * p + 1) * N_CLS + k] : 0.f;
        W2p[i] = make_float2(lo, hi);
    }
    for (int p = tid; p < 96; p += 256) {
        float lo = (2 * p < HID) ? b1[2 * p] : 0.f;
        float hi = (2 * p + 1 < HID) ? b1[2 * p + 1] : 0.f;
        b1p[p] = make_float2(lo, hi);
    }
    __syncthreads();

    int warp = tid >> 5, lane = tid & 31;
    int node = blockIdx.x * 8 + warp;
    if (node >= N_NODES) return;

    float2 a0 = make_float2(0.f, 0.f), a1 = a0, a2 = a0;
    int beg = g_rowptr[node], end = g_rowptr[node + 1];
    const uint32_t* __restrict__ hbase = (const uint32_t*)g_h16;
    const int* __restrict__ colp = g_col;
#pragma unroll 2
    for (int e = beg; e < end; e++) {
        int s = __ldg(colp + e);
        const uint32_t* hp = hbase + (size_t)s * NP2;
        uint32_t w0 = __ldg(hp + lane);
        uint32_t w1 = __ldg(hp + lane + 32);
        uint32_t w2 = (lane < 16) ? __ldg(hp + lane + 64) : 0u;
        float2 f0 = __half22float2(*(__half2*)&w0);
        float2 f1 = __half22float2(*(__half2*)&w1);
        float2 f2 = __half22float2(*(__half2*)&w2);
        a0.x += f0.x; a0.y += f0.y;
        a1.x += f1.x; a1.y += f1.y;
        a2.x += f2.x; a2.y += f2.y;
    }
    {
        const uint32_t* hp = hbase + (size_t)node * NP2;
        uint32_t w0 = hp[lane];
        uint32_t w1 = hp[lane + 32];
        uint32_t w2 = (lane < 16) ? hp[lane + 64] : 0u;
        float2 f0 = __half22float2(*(__half2*)&w0);
        float2 f1 = __half22float2(*(__half2*)&w1);
        float2 f2 = __half22float2(*(__half2*)&w2);
        a0.x += f0.x; a0.y += f0.y;
        a1.x += f1.x; a1.y += f1.y;
        a2.x += f2.x; a2.y += f2.y;
    }
    float di = g_dis[node];
    float2 bb0 = b1p[lane], bb1 = b1p[lane + 32], bb2 = b1p[lane + 64];
    float2 u0 = make_float2(fmaxf(fmaf(di, a0.x, bb0.x), 0.f),
                            fmaxf(fmaf(di, a0.y, bb0.y), 0.f));
    float2 u1 = make_float2(fmaxf(fmaf(di, a1.x, bb1.x), 0.f),
                            fmaxf(fmaf(di, a1.y, bb1.y), 0.f));
    float2 u2 = make_float2(fmaxf(fmaf(di, a2.x, bb2.x), 0.f),
                            fmaxf(fmaf(di, a2.y, bb2.y), 0.f));
    if (lane >= 16) { u2.x = 0.f; u2.y = 0.f; }

    float outk[N_CLS];
#pragma unroll
    for (int k = 0; k < N_CLS; k++) {
        float2 w0 = W2p[lane * N_CLS + k];
        float2 w1 = W2p[(lane + 32) * N_CLS + k];
        float2 w2 = W2p[(lane + 64) * N_CLS + k];
        float p = u0.x * w0.x + u0.y * w0.y
                + u1.x * w1.x + u1.y * w1.y
                + u2.x * w2.x + u2.y * w2.y;
#pragma unroll
        for (int o = 16; o > 0; o >>= 1) p += __shfl_xor_sync(0xffffffffu, p, o);
        outk[k] = p;
    }
    if (lane == 0) {
#pragma unroll
        for (int k = 0; k < N_CLS; k++)
            g_h2[(size_t)node * H2W + k] = di * outk[k];
    }
}

// ---------------- Agg2 + bias + log_softmax ---------------------------------
__global__ void __launch_bounds__(256) k_agg2(const float* __restrict__ b2,
                                              float* __restrict__ out) {
    int i = blockIdx.x * blockDim.x + threadIdx.x;
    if (i >= N_NODES) return;

    float a0 = 0.f, a1 = 0.f, a2 = 0.f, a3 = 0.f, a4 = 0.f, a5 = 0.f, a6 = 0.f;

    int beg = g_rowptr[i], end = g_rowptr[i + 1];
    const int* __restrict__ colp = g_col;
#pragma unroll 2
    for (int e = beg; e < end; e++) {
        int s = __ldg(colp + e);
        const float4* p = (const float4*)(g_h2 + (size_t)s * H2W);
        float4 A = __ldg(p);
        float4 B = __ldg(p + 1);
        a0 += A.x; a1 += A.y; a2 += A.z; a3 += A.w;
        a4 += B.x; a5 += B.y; a6 += B.z;
    }
    {
        const float4* p = (const float4*)(g_h2 + (size_t)i * H2W);
        float4 A = *p;
        float4 B = *(p + 1);
        a0 += A.x; a1 += A.y; a2 += A.z; a3 += A.w;
        a4 += B.x; a5 += B.y; a6 += B.z;
    }
    float di = g_dis[i];
    float v[N_CLS];
    v[0] = fmaf(di, a0, __ldg(b2 + 0));
    v[1] = fmaf(di, a1, __ldg(b2 + 1));
    v[2] = fmaf(di, a2, __ldg(b2 + 2));
    v[3] = fmaf(di, a3, __ldg(b2 + 3));
    v[4] = fmaf(di, a4, __ldg(b2 + 4));
    v[5] = fmaf(di, a5, __ldg(b2 + 5));
    v[6] = fmaf(di, a6, __ldg(b2 + 6));

    float m = v[0];
#pragma unroll
    for (int k = 1; k < N_CLS; k++) m = fmaxf(m, v[k]);
    float s = 0.f;
#pragma unroll
    for (int k = 0; k < N_CLS; k++) s += expf(v[k] - m);
    float lse = m + logf(s);
#pragma unroll
    for (int k = 0; k < N_CLS; k++) out[(size_t)i * N_CLS + k] = v[k] - lse;
}

// ---------------- launch -----------------------------------------------------
extern "C" void kernel_launch(void* const* d_in, const int* in_sizes, int n_in,
                              void* d_out, int out_size) {
    const float* x  = (const float*)d_in[0];
    const int*   ei = (const int*)d_in[1];
    const float* W1 = (const float*)d_in[2];
    const float* b1 = (const float*)d_in[3];
    const float* W2 = (const float*)d_in[4];
    const float* b2 = (const float*)d_in[5];
    float* out = (float*)d_out;

    const int* src = ei;
    const int* dst = ei + N_EDGES;

    cudaFuncSetAttribute(k_gemm_mma, cudaFuncAttributeMaxDynamicSharedMemorySize, SMEM_GEMM);

    k_setup<<<(N_NODES + 255) / 256, 256>>>(W1);                   // 0 (prepw+init)
    k_count<<<(N_EDGES + 255) / 256, 256>>>(dst);                  // 1
    k_scan1<<<SCAN_BLOCKS, 1024>>>();                              // 2
    k_scan3m<<<SCAN_BLOCKS, 1024>>>();                             // 3
    k_fill<<<(N_EDGES + 255) / 256, 256>>>(src, dst);              // 4
    k_gemm_mma<<<(N_NODES + 127) / 128, 256, SMEM_GEMM>>>(x);      // 5
    k_agg1<<<(N_NODES + 7) / 8, 256>>>(b1, W2);                    // 6
    k_agg2<<<(N_NODES + 255) / 256, 256>>>(b2, out);               // 7
}